// round 3
// baseline (speedup 1.0000x reference)
#include <cuda_runtime.h>
#include <math.h>

#define BB 2
#define TT 2048
#define CC 1024
#define C3 3072
#define HH 16
#define HD 64

// -------- scratch (static device globals; allocation-free) --------
__device__ float g_h  [4096*1024];
__device__ float g_qkv[4096*3072];
__device__ float g_y  [4096*1024];
__device__ float g_x2 [4096*1024];
__device__ float g_h2 [4096*1024];
__device__ float g_m  [4096*4096];

// -------- reductions --------
__device__ __forceinline__ float warpReduceSum(float v){
  #pragma unroll
  for (int o=16;o;o>>=1) v += __shfl_xor_sync(0xffffffffu, v, o);
  return v;
}
__device__ __forceinline__ float warpReduceMax(float v){
  #pragma unroll
  for (int o=16;o;o>>=1) v = fmaxf(v, __shfl_xor_sync(0xffffffffu, v, o));
  return v;
}
__device__ float blockReduceSum(float v){
  __shared__ float s[8];
  int lane = threadIdx.x & 31, wid = threadIdx.x >> 5;
  v = warpReduceSum(v);
  __syncthreads();
  if (lane==0) s[wid]=v;
  __syncthreads();
  if (wid==0){
    float t = (lane < 8) ? s[lane] : 0.f;
    t = warpReduceSum(t);
    if (lane==0) s[0]=t;
  }
  __syncthreads();
  return s[0];
}
__device__ float blockReduceMax(float v){
  __shared__ float s[8];
  int lane = threadIdx.x & 31, wid = threadIdx.x >> 5;
  v = warpReduceMax(v);
  __syncthreads();
  if (lane==0) s[wid]=v;
  __syncthreads();
  if (wid==0){
    float t = (lane < 8) ? s[lane] : -INFINITY;
    t = warpReduceMax(t);
    if (lane==0) s[0]=t;
  }
  __syncthreads();
  return s[0];
}

__device__ __forceinline__ float gelu_f(float x){
  float x3 = x*x*x;
  return 0.5f*x*(1.f + tanhf(0.7978845608028654f*(x + 0.044715f*x3)));
}

// -------- LayerNorm: one block per row of 1024 --------
__global__ void __launch_bounds__(256) ln_kernel(const float* __restrict__ x,
                                                 const float* __restrict__ w,
                                                 const float* __restrict__ b,
                                                 float* __restrict__ out){
  size_t row = blockIdx.x;
  const float4* xr = (const float4*)(x + row*CC);
  float4 f = xr[threadIdx.x];
  float mean = blockReduceSum(f.x+f.y+f.z+f.w) * (1.f/CC);
  float dx=f.x-mean, dy=f.y-mean, dz=f.z-mean, dw=f.w-mean;
  float var = blockReduceSum(dx*dx+dy*dy+dz*dz+dw*dw) * (1.f/CC);
  float rs = rsqrtf(var + 1e-5f);
  float4 wv = ((const float4*)w)[threadIdx.x];
  float4 bv = ((const float4*)b)[threadIdx.x];
  float4 o;
  o.x = dx*rs*wv.x + bv.x;
  o.y = dy*rs*wv.y + bv.y;
  o.z = dz*rs*wv.z + bv.z;
  o.w = dw*rs*wv.w + bv.w;
  ((float4*)(out + row*CC))[threadIdx.x] = o;
}

// -------- generic fp32 GEMM, 128x128 block tile, 8x8 per thread, double-buffered --------
// OP 0: C = A@B + bias ; OP 1: C = gelu(A@B + bias) ; OP 2: C = A@B + bias + R
template<int OP>
__global__ void __launch_bounds__(256,2) gemm_f32(
    const float* __restrict__ A, const float* __restrict__ B,
    const float* __restrict__ bias, const float* __restrict__ R,
    float* __restrict__ C, int M, int N, int K)
{
  __shared__ float As[2][16][128];
  __shared__ float Bs[2][16][128];
  const int tid = threadIdx.x;
  const int bm = blockIdx.y * 128;
  const int bn = blockIdx.x * 128;
  const int rb = (tid >> 4) << 3;
  const int cb = (tid & 15) << 3;

  const int s0 = tid*2, s1 = tid*2+1;
  const int rA0 = s0>>2, k40 = (s0&3)*4;
  const int rA1 = s1>>2, k41 = (s1&3)*4;
  const int kB0 = s0>>5, c40 = (s0&31)*4;
  const int kB1 = s1>>5, c41 = (s1&31)*4;

  const float* Abase = A + (size_t)bm * K;
  const float* Bbase = B + bn;

  float acc[8][8];
  #pragma unroll
  for (int i=0;i<8;i++)
    #pragma unroll
    for (int j=0;j<8;j++) acc[i][j]=0.f;

  const int nk = K >> 4;
  float4 a0,a1,b0,b1;

  a0 = *(const float4*)(Abase + (size_t)rA0*K + k40);
  a1 = *(const float4*)(Abase + (size_t)rA1*K + k41);
  b0 = *(const float4*)(Bbase + (size_t)kB0*N + c40);
  b1 = *(const float4*)(Bbase + (size_t)kB1*N + c41);
  As[0][k40+0][rA0]=a0.x; As[0][k40+1][rA0]=a0.y; As[0][k40+2][rA0]=a0.z; As[0][k40+3][rA0]=a0.w;
  As[0][k41+0][rA1]=a1.x; As[0][k41+1][rA1]=a1.y; As[0][k41+2][rA1]=a1.z; As[0][k41+3][rA1]=a1.w;
  *(float4*)&Bs[0][kB0][c40] = b0;
  *(float4*)&Bs[0][kB1][c41] = b1;
  __syncthreads();

  for (int kt=0; kt<nk; kt++){
    int buf = kt & 1;
    if (kt+1 < nk){
      const float* Ab = Abase + (kt+1)*16;
      const float* Bb = Bbase + (size_t)((kt+1)*16)*N;
      a0 = *(const float4*)(Ab + (size_t)rA0*K + k40);
      a1 = *(const float4*)(Ab + (size_t)rA1*K + k41);
      b0 = *(const float4*)(Bb + (size_t)kB0*N + c40);
      b1 = *(const float4*)(Bb + (size_t)kB1*N + c41);
    }
    #pragma unroll
    for (int k=0;k<16;k++){
      float4 x0 = *(const float4*)&As[buf][k][rb];
      float4 x1 = *(const float4*)&As[buf][k][rb+4];
      float4 y0 = *(const float4*)&Bs[buf][k][cb];
      float4 y1 = *(const float4*)&Bs[buf][k][cb+4];
      float ar[8]={x0.x,x0.y,x0.z,x0.w,x1.x,x1.y,x1.z,x1.w};
      float br[8]={y0.x,y0.y,y0.z,y0.w,y1.x,y1.y,y1.z,y1.w};
      #pragma unroll
      for (int i=0;i<8;i++)
        #pragma unroll
        for (int j=0;j<8;j++)
          acc[i][j] = fmaf(ar[i], br[j], acc[i][j]);
    }
    if (kt+1 < nk){
      int nb = buf^1;
      As[nb][k40+0][rA0]=a0.x; As[nb][k40+1][rA0]=a0.y; As[nb][k40+2][rA0]=a0.z; As[nb][k40+3][rA0]=a0.w;
      As[nb][k41+0][rA1]=a1.x; As[nb][k41+1][rA1]=a1.y; As[nb][k41+2][rA1]=a1.z; As[nb][k41+3][rA1]=a1.w;
      *(float4*)&Bs[nb][kB0][c40] = b0;
      *(float4*)&Bs[nb][kB1][c41] = b1;
      __syncthreads();
    }
  }

  float bvv[8];
  #pragma unroll
  for (int j=0;j<8;j++) bvv[j] = bias[bn+cb+j];
  #pragma unroll
  for (int i=0;i<8;i++){
    size_t roff = (size_t)(bm+rb+i)*N + bn + cb;
    float v[8];
    #pragma unroll
    for (int j=0;j<8;j++) v[j] = acc[i][j] + bvv[j];
    if (OP==1){
      #pragma unroll
      for (int j=0;j<8;j++) v[j] = gelu_f(v[j]);
    }
    if (OP==2){
      float4 r0 = *(const float4*)(R+roff);
      float4 r1 = *(const float4*)(R+roff+4);
      v[0]+=r0.x; v[1]+=r0.y; v[2]+=r0.z; v[3]+=r0.w;
      v[4]+=r1.x; v[5]+=r1.y; v[6]+=r1.z; v[7]+=r1.w;
    }
    float4 o0 = make_float4(v[0],v[1],v[2],v[3]);
    float4 o1 = make_float4(v[4],v[5],v[6],v[7]);
    *(float4*)(C+roff)   = o0;
    *(float4*)(C+roff+4) = o1;
  }
}

// -------- attention raw scores: S = Q K^T / 8 per head, causal tile skipping --------
__global__ void __launch_bounds__(256) attn_scores(const float* __restrict__ qkv,
                                                   float* __restrict__ att){
  int kt = blockIdx.x, qt = blockIdx.y, z = blockIdx.z; // z = b*H + h
  if (kt > qt) return;
  int b = z >> 4, h = z & 15;
  __shared__ float Qs[32][128];
  __shared__ float Ks[32][128];
  const int tid = threadIdx.x;
  const int rb = (tid >> 4) << 3;
  const int cb = (tid & 15) << 3;
  const float* qbase = qkv + (size_t)b*TT*C3 + h*HD;
  const float* kbase = qbase + CC;

  float acc[8][8];
  #pragma unroll
  for (int i=0;i<8;i++)
    #pragma unroll
    for (int j=0;j<8;j++) acc[i][j]=0.f;

  #pragma unroll
  for (int dk=0; dk<HD; dk+=32){
    #pragma unroll
    for (int j=0;j<4;j++){
      int s = tid*4+j;
      int row = s>>3, c4 = (s&7)*4;
      float4 v = *(const float4*)(qbase + (size_t)(qt*128+row)*C3 + dk + c4);
      Qs[c4+0][row]=v.x; Qs[c4+1][row]=v.y; Qs[c4+2][row]=v.z; Qs[c4+3][row]=v.w;
      float4 u = *(const float4*)(kbase + (size_t)(kt*128+row)*C3 + dk + c4);
      Ks[c4+0][row]=u.x; Ks[c4+1][row]=u.y; Ks[c4+2][row]=u.z; Ks[c4+3][row]=u.w;
    }
    __syncthreads();
    #pragma unroll
    for (int k=0;k<32;k++){
      float4 x0 = *(const float4*)&Qs[k][rb];
      float4 x1 = *(const float4*)&Qs[k][rb+4];
      float4 y0 = *(const float4*)&Ks[k][cb];
      float4 y1 = *(const float4*)&Ks[k][cb+4];
      float ar[8]={x0.x,x0.y,x0.z,x0.w,x1.x,x1.y,x1.z,x1.w};
      float br[8]={y0.x,y0.y,y0.z,y0.w,y1.x,y1.y,y1.z,y1.w};
      #pragma unroll
      for (int i=0;i<8;i++)
        #pragma unroll
        for (int j=0;j<8;j++)
          acc[i][j] = fmaf(ar[i], br[j], acc[i][j]);
    }
    __syncthreads();
  }
  float* out = att + (size_t)z*TT*TT;
  #pragma unroll
  for (int i=0;i<8;i++){
    size_t roff = (size_t)(qt*128+rb+i)*TT + kt*128+cb;
    float4 o0 = make_float4(acc[i][0]*0.125f, acc[i][1]*0.125f, acc[i][2]*0.125f, acc[i][3]*0.125f);
    float4 o1 = make_float4(acc[i][4]*0.125f, acc[i][5]*0.125f, acc[i][6]*0.125f, acc[i][7]*0.125f);
    *(float4*)(out+roff)   = o0;
    *(float4*)(out+roff+4) = o1;
  }
}

// -------- causal softmax in-place over att rows; zeros above diagonal --------
__global__ void __launch_bounds__(256) softmax_kernel(float* __restrict__ att){
  size_t r = blockIdx.x;
  int q = (int)(r & (TT-1));
  float* row = att + r * (size_t)TT;
  int L = q+1;
  float vals[8];
  int cnt=0;
  float mx = -INFINITY;
  for (int i=threadIdx.x; i<L; i+=256){
    float v = row[i];
    vals[cnt++] = v;
    mx = fmaxf(mx, v);
  }
  mx = blockReduceMax(mx);
  float s=0.f;
  for (int c2=0;c2<cnt;c2++){ vals[c2] = __expf(vals[c2]-mx); s += vals[c2]; }
  s = blockReduceSum(s);
  float inv = 1.f/s;
  cnt=0;
  for (int i=threadIdx.x; i<L; i+=256) row[i] = vals[cnt++]*inv;
  for (int i=L+threadIdx.x; i<TT; i+=256) row[i] = 0.f;
}

// -------- y = att @ V per head (skips all-zero k tiles above diagonal) --------
__global__ void __launch_bounds__(256) attn_av(const float* __restrict__ att,
                                               const float* __restrict__ qkv,
                                               float* __restrict__ y){
  int qt = blockIdx.x, z = blockIdx.y;
  int b = z >> 4, h = z & 15;
  __shared__ float As[32][128];
  __shared__ float Vs[32][64];
  const int tid = threadIdx.x;
  const int rb  = (tid >> 4) << 3;
  const int cb4 = (tid & 15) << 2;
  const float* arow  = att + (size_t)z*TT*TT + (size_t)qt*128*TT;
  const float* vbase = qkv + (size_t)b*TT*C3 + 2*CC + h*HD;

  float acc[8][4];
  #pragma unroll
  for (int i=0;i<8;i++)
    #pragma unroll
    for (int j=0;j<4;j++) acc[i][j]=0.f;

  int nchunks = (qt+1)*4; // (qt+1)*128 / 32
  for (int c=0;c<nchunks;c++){
    int k0 = c*32;
    #pragma unroll
    for (int j=0;j<4;j++){
      int s = tid*4+j;
      int row = s>>3, c4 = (s&7)*4;
      float4 v = *(const float4*)(arow + (size_t)row*TT + k0 + c4);
      As[c4+0][row]=v.x; As[c4+1][row]=v.y; As[c4+2][row]=v.z; As[c4+3][row]=v.w;
    }
    #pragma unroll
    for (int j=0;j<2;j++){
      int s = tid*2+j;
      int kk = s>>4, c4 = (s&15)*4;
      float4 v = *(const float4*)(vbase + (size_t)(k0+kk)*C3 + c4);
      *(float4*)&Vs[kk][c4] = v;
    }
    __syncthreads();
    #pragma unroll
    for (int k=0;k<32;k++){
      float4 x0 = *(const float4*)&As[k][rb];
      float4 x1 = *(const float4*)&As[k][rb+4];
      float4 vv = *(const float4*)&Vs[k][cb4];
      float ar[8]={x0.x,x0.y,x0.z,x0.w,x1.x,x1.y,x1.z,x1.w};
      #pragma unroll
      for (int i=0;i<8;i++){
        acc[i][0] = fmaf(ar[i], vv.x, acc[i][0]);
        acc[i][1] = fmaf(ar[i], vv.y, acc[i][1]);
        acc[i][2] = fmaf(ar[i], vv.z, acc[i][2]);
        acc[i][3] = fmaf(ar[i], vv.w, acc[i][3]);
      }
    }
    __syncthreads();
  }
  #pragma unroll
  for (int i=0;i<8;i++){
    size_t roff = ((size_t)(b*TT + qt*128 + rb + i))*CC + h*HD + cb4;
    *(float4*)(y+roff) = make_float4(acc[i][0],acc[i][1],acc[i][2],acc[i][3]);
  }
}

extern "C" void kernel_launch(void* const* d_in, const int* in_sizes, int n_in,
                              void* d_out, int out_size){
  (void)in_sizes; (void)n_in; (void)out_size;
  const float* x         = (const float*)d_in[0];
  // d_in[1] = attn_mask (tril; implemented as causal logic)
  const float* w_attn    = (const float*)d_in[2];
  const float* b_attn    = (const float*)d_in[3];
  const float* w_proj    = (const float*)d_in[4];
  const float* b_proj    = (const float*)d_in[5];
  const float* ln1_w     = (const float*)d_in[6];
  const float* ln1_b     = (const float*)d_in[7];
  const float* ln2_w     = (const float*)d_in[8];
  const float* ln2_b     = (const float*)d_in[9];
  const float* w_fc      = (const float*)d_in[10];
  const float* b_fc      = (const float*)d_in[11];
  const float* w_fc_proj = (const float*)d_in[12];
  const float* b_fc_proj = (const float*)d_in[13];

  float* out_x = (float*)d_out;
  float* att   = (float*)d_out + (size_t)BB*TT*CC;   // 4,194,304 offset

  float *h, *qkv, *y, *x2, *h2, *m;
  cudaGetSymbolAddress((void**)&h,   g_h);
  cudaGetSymbolAddress((void**)&qkv, g_qkv);
  cudaGetSymbolAddress((void**)&y,   g_y);
  cudaGetSymbolAddress((void**)&x2,  g_x2);
  cudaGetSymbolAddress((void**)&h2,  g_h2);
  cudaGetSymbolAddress((void**)&m,   g_m);

  const int M = BB*TT;  // 4096

  ln_kernel<<<M, 256>>>(x, ln1_w, ln1_b, h);
  gemm_f32<0><<<dim3(3*CC/128, M/128), 256>>>(h, w_attn, b_attn, nullptr, qkv, M, 3*CC, CC);
  attn_scores<<<dim3(TT/128, TT/128, BB*HH), 256>>>(qkv, att);
  softmax_kernel<<<BB*HH*TT, 256>>>(att);
  attn_av<<<dim3(TT/128, BB*HH), 256>>>(att, qkv, y);
  gemm_f32<2><<<dim3(CC/128, M/128), 256>>>(y, w_proj, b_proj, x, x2, M, CC, CC);
  ln_kernel<<<M, 256>>>(x2, ln2_w, ln2_b, h2);
  gemm_f32<1><<<dim3(4*CC/128, M/128), 256>>>(h2, w_fc, b_fc, nullptr, m, M, 4*CC, CC);
  gemm_f32<2><<<dim3(CC/128, M/128), 256>>>(m, w_fc_proj, b_fc_proj, x2, out_x, M, CC, 4*CC);
}

// round 6
// speedup vs baseline: 1.9440x; 1.9440x over previous
#include <cuda_runtime.h>
#include <cuda_bf16.h>
#include <math.h>
#include <stdint.h>

#define BB 2
#define TT 2048
#define CC 1024
#define C3 3072
#define HH 16
#define HD 64
#define MM 4096

// ---------------- scratch (static device globals; allocation-free) ----------------
__device__ float g_qkv[MM * C3];
__device__ float g_x2 [MM * CC];
__device__ __nv_bfloat16 g_h_hi [MM * CC],   g_h_lo [MM * CC];
__device__ __nv_bfloat16 g_h2_hi[MM * CC],   g_h2_lo[MM * CC];
__device__ __nv_bfloat16 g_y_hi [MM * CC],   g_y_lo [MM * CC];
__device__ __nv_bfloat16 g_m_hi [MM * 4096], g_m_lo [MM * 4096];
__device__ __nv_bfloat16 g_wat_hi[C3 * CC],  g_wat_lo[C3 * CC];
__device__ __nv_bfloat16 g_wp_hi [CC * CC],  g_wp_lo [CC * CC];
__device__ __nv_bfloat16 g_wf_hi [4096 * CC],g_wf_lo [4096 * CC];
__device__ __nv_bfloat16 g_wfp_hi[CC * 4096],g_wfp_lo[CC * 4096];

// ---------------- helpers ----------------
__device__ __forceinline__ uint32_t smem_u32(const void* p){
  uint32_t a;
  asm("{ .reg .u64 t; cvta.to.shared.u64 t, %1; cvt.u32.u64 %0, t; }" : "=r"(a) : "l"(p));
  return a;
}
__device__ __forceinline__ void cp16(uint32_t dst, const void* src){
  asm volatile("cp.async.cg.shared.global [%0], [%1], 16;\n" :: "r"(dst), "l"(src));
}
__device__ __forceinline__ void cp_commit(){ asm volatile("cp.async.commit_group;\n"); }
__device__ __forceinline__ void cp_wait1(){ asm volatile("cp.async.wait_group 1;\n" ::: "memory"); }
__device__ __forceinline__ void cp_wait0(){ asm volatile("cp.async.wait_group 0;\n" ::: "memory"); }

__device__ __forceinline__ void mma16816(float* d, const uint32_t* a, uint32_t b0, uint32_t b1){
  asm volatile("mma.sync.aligned.m16n8k16.row.col.f32.bf16.bf16.f32 "
    "{%0,%1,%2,%3}, {%4,%5,%6,%7}, {%8,%9}, {%0,%1,%2,%3};"
    : "+f"(d[0]), "+f"(d[1]), "+f"(d[2]), "+f"(d[3])
    : "r"(a[0]), "r"(a[1]), "r"(a[2]), "r"(a[3]), "r"(b0), "r"(b1));
}

__device__ __forceinline__ float warpReduceSum(float v){
  #pragma unroll
  for (int o=16;o;o>>=1) v += __shfl_xor_sync(0xffffffffu, v, o);
  return v;
}
__device__ __forceinline__ float warpReduceMax(float v){
  #pragma unroll
  for (int o=16;o;o>>=1) v = fmaxf(v, __shfl_xor_sync(0xffffffffu, v, o));
  return v;
}
__device__ float blockReduceSum(float v){
  __shared__ float s[8];
  int lane = threadIdx.x & 31, wid = threadIdx.x >> 5;
  v = warpReduceSum(v);
  __syncthreads();
  if (lane==0) s[wid]=v;
  __syncthreads();
  if (wid==0){
    float t = (lane < 8) ? s[lane] : 0.f;
    t = warpReduceSum(t);
    if (lane==0) s[0]=t;
  }
  __syncthreads();
  return s[0];
}
__device__ float blockReduceMax(float v){
  __shared__ float s[8];
  int lane = threadIdx.x & 31, wid = threadIdx.x >> 5;
  v = warpReduceMax(v);
  __syncthreads();
  if (lane==0) s[wid]=v;
  __syncthreads();
  if (wid==0){
    float t = (lane < 8) ? s[lane] : -INFINITY;
    t = warpReduceMax(t);
    if (lane==0) s[0]=t;
  }
  __syncthreads();
  return s[0];
}

__device__ __forceinline__ float gelu_f(float x){
  float x3 = x*x*x;
  return 0.5f*x*(1.f + tanhf(0.7978845608028654f*(x + 0.044715f*x3)));
}
__device__ __forceinline__ void split_bf16(float v, __nv_bfloat16& h, __nv_bfloat16& l){
  h = __float2bfloat16(v);
  l = __float2bfloat16(v - __bfloat162float(h));
}

// ---------------- LayerNorm -> bf16 hi/lo pair ----------------
__global__ void __launch_bounds__(256) ln_split(const float* __restrict__ x,
                                                const float* __restrict__ w,
                                                const float* __restrict__ b,
                                                __nv_bfloat16* __restrict__ ohi,
                                                __nv_bfloat16* __restrict__ olo){
  size_t row = blockIdx.x;
  float4 f = ((const float4*)(x + row*CC))[threadIdx.x];
  float mean = blockReduceSum(f.x+f.y+f.z+f.w) * (1.f/CC);
  float dx=f.x-mean, dy=f.y-mean, dz=f.z-mean, dw=f.w-mean;
  float var = blockReduceSum(dx*dx+dy*dy+dz*dz+dw*dw) * (1.f/CC);
  float rs = rsqrtf(var + 1e-5f);
  float4 wv = ((const float4*)w)[threadIdx.x];
  float4 bv = ((const float4*)b)[threadIdx.x];
  float o[4];
  o[0]=dx*rs*wv.x+bv.x; o[1]=dy*rs*wv.y+bv.y; o[2]=dz*rs*wv.z+bv.z; o[3]=dw*rs*wv.w+bv.w;
  __align__(8) __nv_bfloat16 hh[4], ll[4];
  #pragma unroll
  for (int j=0;j<4;j++) split_bf16(o[j], hh[j], ll[j]);
  size_t off = row*CC + threadIdx.x*4;
  *(uint2*)(ohi+off) = *(uint2*)hh;
  *(uint2*)(olo+off) = *(uint2*)ll;
}

// ---------------- weight split+transpose: W[K,N] fp32 -> T[N,K] bf16 hi/lo ----------------
__global__ void wsplitT(const float* __restrict__ W, __nv_bfloat16* __restrict__ Thi,
                        __nv_bfloat16* __restrict__ Tlo, int K, int N){
  __shared__ float t[32][33];
  int n0 = blockIdx.x*32, k0 = blockIdx.y*32;
  int tx = threadIdx.x, ty = threadIdx.y; // (32,8)
  #pragma unroll
  for (int j=0;j<4;j++)
    t[ty+8*j][tx] = W[(size_t)(k0+ty+8*j)*N + n0+tx];
  __syncthreads();
  #pragma unroll
  for (int j=0;j<4;j++){
    int n = ty+8*j;
    float v = t[tx][n];
    __nv_bfloat16 h, l; split_bf16(v, h, l);
    size_t off = (size_t)(n0+n)*K + k0+tx;
    Thi[off]=h; Tlo[off]=l;
  }
}

// ---------------- mma.sync bf16-pair GEMM: C[M,N] = A[M,K] @ B[N,K]^T ----------------
// Block 256 thr (8 warps), tile 128x128, warp tile 32x64, K chunk 32, double-buffered.
// Smem per stage (bf16 elems, padded stride 40): AH=0, AL=5120, BH=10240, BL=15360 ; stage=20480
// OP 0: C = fp32(A@B + bias)
// OP 1: Chi/Clo = split(gelu(A@B + bias))
// OP 2: C = fp32(A@B + bias + R)
#define STRD 40
#define STG_ELEMS 20480
template<int OP>
__global__ void __launch_bounds__(256) gemm_mma(
    const __nv_bfloat16* __restrict__ Ahi, const __nv_bfloat16* __restrict__ Alo,
    const __nv_bfloat16* __restrict__ Bhi, const __nv_bfloat16* __restrict__ Blo,
    const float* __restrict__ bias, const float* __restrict__ R,
    float* __restrict__ C, __nv_bfloat16* __restrict__ Chi, __nv_bfloat16* __restrict__ Clo,
    int M, int N, int K)
{
  extern __shared__ __nv_bfloat16 sm[];
  const int tid = threadIdx.x, lane = tid & 31, wid = tid >> 5;
  const int wrow = wid >> 1, wcol = wid & 1;
  const int bm = blockIdx.y*128, bn = blockIdx.x*128;
  const uint32_t sb = smem_u32(sm);

  const __nv_bfloat16* Abh = Ahi + (size_t)bm*K;
  const __nv_bfloat16* Abl = Alo + (size_t)bm*K;
  const __nv_bfloat16* Bbh = Bhi + (size_t)bn*K;
  const __nv_bfloat16* Bbl = Blo + (size_t)bn*K;

  const int lrow = tid >> 2;       // 0..63
  const int lseg = tid & 3;        // 16B seg within 64B of k-chunk row

  auto load_stage = [&](int s, int kt){
    uint32_t base = sb + (uint32_t)(s*STG_ELEMS)*2u;
    size_t kof = (size_t)kt*32 + lseg*8;
    #pragma unroll
    for (int r=0; r<2; r++){
      int row = lrow + r*64;
      uint32_t so = base + (uint32_t)(row*STRD + lseg*8)*2u;
      size_t go = (size_t)row*K + kof;
      cp16(so,              Abh + go);
      cp16(so + 5120*2,     Abl + go);
      cp16(so + 10240*2,    Bbh + go);
      cp16(so + 15360*2,    Bbl + go);
    }
    cp_commit();
  };

  float acc[2][8][4];
  #pragma unroll
  for (int mi=0;mi<2;mi++)
    #pragma unroll
    for (int ni=0;ni<8;ni++)
      #pragma unroll
      for (int j=0;j<4;j++) acc[mi][ni][j]=0.f;

  const int NK = K >> 5;
  load_stage(0, 0);

  for (int kt = 0; kt < NK; kt++){
    int s = kt & 1;
    if (kt+1 < NK){ load_stage(s^1, kt+1); cp_wait1(); }
    else          { cp_wait0(); }
    __syncthreads();

    const __nv_bfloat16* As = sm + s*STG_ELEMS;
    const __nv_bfloat16* Bs = As + 10240;
    #pragma unroll
    for (int kk = 0; kk < 2; kk++){
      int k0 = kk*16 + (lane&3)*2;
      uint32_t ah[2][4], al[2][4];
      #pragma unroll
      for (int mi=0;mi<2;mi++){
        int m0 = wrow*32 + mi*16 + (lane>>2);
        ah[mi][0] = *(const uint32_t*)&As[ m0   *STRD + k0  ];
        ah[mi][1] = *(const uint32_t*)&As[(m0+8)*STRD + k0  ];
        ah[mi][2] = *(const uint32_t*)&As[ m0   *STRD + k0+8];
        ah[mi][3] = *(const uint32_t*)&As[(m0+8)*STRD + k0+8];
        al[mi][0] = *(const uint32_t*)&As[5120 +  m0   *STRD + k0  ];
        al[mi][1] = *(const uint32_t*)&As[5120 + (m0+8)*STRD + k0  ];
        al[mi][2] = *(const uint32_t*)&As[5120 +  m0   *STRD + k0+8];
        al[mi][3] = *(const uint32_t*)&As[5120 + (m0+8)*STRD + k0+8];
      }
      #pragma unroll
      for (int ni=0;ni<8;ni++){
        int n0 = wcol*64 + ni*8 + (lane>>2);
        uint32_t bh0 = *(const uint32_t*)&Bs[ n0*STRD + k0  ];
        uint32_t bh1 = *(const uint32_t*)&Bs[ n0*STRD + k0+8];
        uint32_t bl0 = *(const uint32_t*)&Bs[5120 + n0*STRD + k0  ];
        uint32_t bl1 = *(const uint32_t*)&Bs[5120 + n0*STRD + k0+8];
        #pragma unroll
        for (int mi=0;mi<2;mi++){
          mma16816(acc[mi][ni], ah[mi], bh0, bh1);
          mma16816(acc[mi][ni], ah[mi], bl0, bl1);
          mma16816(acc[mi][ni], al[mi], bh0, bh1);
        }
      }
    }
    __syncthreads();
  }

  // ---------------- epilogue ----------------
  #pragma unroll
  for (int mi=0;mi<2;mi++){
    int row0 = bm + wrow*32 + mi*16 + (lane>>2);
    #pragma unroll
    for (int ni=0;ni<8;ni++){
      int col = bn + wcol*64 + ni*8 + (lane&3)*2;
      float b0 = bias[col], b1 = bias[col+1];
      float v0 = acc[mi][ni][0] + b0;
      float v1 = acc[mi][ni][1] + b1;
      float v2 = acc[mi][ni][2] + b0;
      float v3 = acc[mi][ni][3] + b1;
      size_t o0 = (size_t)row0*N + col;
      size_t o1 = (size_t)(row0+8)*N + col;
      if (OP == 2){
        float2 r0 = *(const float2*)(R+o0);
        float2 r1 = *(const float2*)(R+o1);
        v0+=r0.x; v1+=r0.y; v2+=r1.x; v3+=r1.y;
      }
      if (OP == 1){
        v0 = gelu_f(v0); v1 = gelu_f(v1); v2 = gelu_f(v2); v3 = gelu_f(v3);
        __nv_bfloat16 h0,l0,h1,l1,h2,l2,h3,l3;
        split_bf16(v0,h0,l0); split_bf16(v1,h1,l1);
        split_bf16(v2,h2,l2); split_bf16(v3,h3,l3);
        *(__nv_bfloat162*)(Chi+o0) = __nv_bfloat162(h0,h1);
        *(__nv_bfloat162*)(Clo+o0) = __nv_bfloat162(l0,l1);
        *(__nv_bfloat162*)(Chi+o1) = __nv_bfloat162(h2,h3);
        *(__nv_bfloat162*)(Clo+o1) = __nv_bfloat162(l2,l3);
      } else {
        *(float2*)(C+o0) = make_float2(v0,v1);
        *(float2*)(C+o1) = make_float2(v2,v3);
      }
    }
  }
}

// ---------------- attention raw scores: S = Q K^T / 8 (fp32 FFMA, causal tile skip) ----------------
__global__ void __launch_bounds__(256) attn_scores(const float* __restrict__ qkv,
                                                   float* __restrict__ att){
  int kt = blockIdx.x, qt = blockIdx.y, z = blockIdx.z;
  if (kt > qt) return;
  int b = z >> 4, h = z & 15;
  __shared__ float Qs[32][128];
  __shared__ float Ks[32][128];
  const int tid = threadIdx.x;
  const int rb = (tid >> 4) << 3;
  const int cb = (tid & 15) << 3;
  const float* qbase = qkv + (size_t)b*TT*C3 + h*HD;
  const float* kbase = qbase + CC;

  float acc[8][8];
  #pragma unroll
  for (int i=0;i<8;i++)
    #pragma unroll
    for (int j=0;j<8;j++) acc[i][j]=0.f;

  #pragma unroll
  for (int dk=0; dk<HD; dk+=32){
    #pragma unroll
    for (int j=0;j<4;j++){
      int s = tid*4+j;
      int row = s>>3, c4 = (s&7)*4;
      float4 v = *(const float4*)(qbase + (size_t)(qt*128+row)*C3 + dk + c4);
      Qs[c4+0][row]=v.x; Qs[c4+1][row]=v.y; Qs[c4+2][row]=v.z; Qs[c4+3][row]=v.w;
      float4 u = *(const float4*)(kbase + (size_t)(kt*128+row)*C3 + dk + c4);
      Ks[c4+0][row]=u.x; Ks[c4+1][row]=u.y; Ks[c4+2][row]=u.z; Ks[c4+3][row]=u.w;
    }
    __syncthreads();
    #pragma unroll
    for (int k=0;k<32;k++){
      float4 x0 = *(const float4*)&Qs[k][rb];
      float4 x1 = *(const float4*)&Qs[k][rb+4];
      float4 y0 = *(const float4*)&Ks[k][cb];
      float4 y1 = *(const float4*)&Ks[k][cb+4];
      float ar[8]={x0.x,x0.y,x0.z,x0.w,x1.x,x1.y,x1.z,x1.w};
      float br[8]={y0.x,y0.y,y0.z,y0.w,y1.x,y1.y,y1.z,y1.w};
      #pragma unroll
      for (int i=0;i<8;i++)
        #pragma unroll
        for (int j=0;j<8;j++)
          acc[i][j] = fmaf(ar[i], br[j], acc[i][j]);
    }
    __syncthreads();
  }
  float* out = att + (size_t)z*TT*TT;
  #pragma unroll
  for (int i=0;i<8;i++){
    size_t roff = (size_t)(qt*128+rb+i)*TT + kt*128+cb;
    *(float4*)(out+roff)   = make_float4(acc[i][0]*0.125f, acc[i][1]*0.125f, acc[i][2]*0.125f, acc[i][3]*0.125f);
    *(float4*)(out+roff+4) = make_float4(acc[i][4]*0.125f, acc[i][5]*0.125f, acc[i][6]*0.125f, acc[i][7]*0.125f);
  }
}

// ---------------- causal softmax in-place (vectorized); zeros above diagonal ----------------
__global__ void __launch_bounds__(256) softmax_kernel(float* __restrict__ att){
  size_t r = blockIdx.x;
  int q = (int)(r & (TT-1));
  float* row = att + r * (size_t)TT;
  int Lr4 = (((q>>7)+1)*128) >> 2;
  float4 vals[2];
  float mx = -INFINITY;
  int n = 0;
  for (int i=threadIdx.x; i<Lr4; i+=256, n++){
    float4 v = ((const float4*)row)[i];
    int b4 = i*4;
    v.x = (b4   <= q) ? v.x : -INFINITY;
    v.y = (b4+1 <= q) ? v.y : -INFINITY;
    v.z = (b4+2 <= q) ? v.z : -INFINITY;
    v.w = (b4+3 <= q) ? v.w : -INFINITY;
    vals[n] = v;
    mx = fmaxf(mx, fmaxf(fmaxf(v.x,v.y), fmaxf(v.z,v.w)));
  }
  mx = blockReduceMax(mx);
  float s = 0.f;
  for (int j=0;j<n;j++){
    vals[j].x = __expf(vals[j].x - mx);
    vals[j].y = __expf(vals[j].y - mx);
    vals[j].z = __expf(vals[j].z - mx);
    vals[j].w = __expf(vals[j].w - mx);
    s += vals[j].x + vals[j].y + vals[j].z + vals[j].w;
  }
  s = blockReduceSum(s);
  float inv = 1.f/s;
  n = 0;
  for (int i=threadIdx.x; i<Lr4; i+=256, n++){
    float4 v = vals[n];
    v.x*=inv; v.y*=inv; v.z*=inv; v.w*=inv;
    ((float4*)row)[i] = v;
  }
  for (int i=Lr4+threadIdx.x; i<TT/4; i+=256)
    ((float4*)row)[i] = make_float4(0.f,0.f,0.f,0.f);
}

// ---------------- y = att @ V per head -> bf16 hi/lo pair ----------------
__global__ void __launch_bounds__(256) attn_av(const float* __restrict__ att,
                                               const float* __restrict__ qkv,
                                               __nv_bfloat16* __restrict__ yhi,
                                               __nv_bfloat16* __restrict__ ylo){
  int qt = blockIdx.x, z = blockIdx.y;
  int b = z >> 4, h = z & 15;
  __shared__ float As[32][128];
  __shared__ float Vs[32][64];
  const int tid = threadIdx.x;
  const int rb  = (tid >> 4) << 3;
  const int cb4 = (tid & 15) << 2;
  const float* arow  = att + (size_t)z*TT*TT + (size_t)qt*128*TT;
  const float* vbase = qkv + (size_t)b*TT*C3 + 2*CC + h*HD;

  float acc[8][4];
  #pragma unroll
  for (int i=0;i<8;i++)
    #pragma unroll
    for (int j=0;j<4;j++) acc[i][j]=0.f;

  int nchunks = (qt+1)*4;
  for (int c=0;c<nchunks;c++){
    int k0 = c*32;
    #pragma unroll
    for (int j=0;j<4;j++){
      int s = tid*4+j;
      int row = s>>3, c4 = (s&7)*4;
      float4 v = *(const float4*)(arow + (size_t)row*TT + k0 + c4);
      As[c4+0][row]=v.x; As[c4+1][row]=v.y; As[c4+2][row]=v.z; As[c4+3][row]=v.w;
    }
    #pragma unroll
    for (int j=0;j<2;j++){
      int s = tid*2+j;
      int kk = s>>4, c4 = (s&15)*4;
      float4 v = *(const float4*)(vbase + (size_t)(k0+kk)*C3 + c4);
      *(float4*)&Vs[kk][c4] = v;
    }
    __syncthreads();
    #pragma unroll
    for (int k=0;k<32;k++){
      float4 x0 = *(const float4*)&As[k][rb];
      float4 x1 = *(const float4*)&As[k][rb+4];
      float4 vv = *(const float4*)&Vs[k][cb4];
      float ar[8]={x0.x,x0.y,x0.z,x0.w,x1.x,x1.y,x1.z,x1.w};
      #pragma unroll
      for (int i=0;i<8;i++){
        acc[i][0] = fmaf(ar[i], vv.x, acc[i][0]);
        acc[i][1] = fmaf(ar[i], vv.y, acc[i][1]);
        acc[i][2] = fmaf(ar[i], vv.z, acc[i][2]);
        acc[i][3] = fmaf(ar[i], vv.w, acc[i][3]);
      }
    }
    __syncthreads();
  }
  #pragma unroll
  for (int i=0;i<8;i++){
    size_t roff = ((size_t)(b*TT + qt*128 + rb + i))*CC + h*HD + cb4;
    __align__(8) __nv_bfloat16 hh[4], ll[4];
    #pragma unroll
    for (int j=0;j<4;j++) split_bf16(acc[i][j], hh[j], ll[j]);
    *(uint2*)(yhi+roff) = *(uint2*)hh;
    *(uint2*)(ylo+roff) = *(uint2*)ll;
  }
}

// ---------------- launch ----------------
extern "C" void kernel_launch(void* const* d_in, const int* in_sizes, int n_in,
                              void* d_out, int out_size){
  (void)in_sizes; (void)n_in; (void)out_size;
  const float* x         = (const float*)d_in[0];
  const float* w_attn    = (const float*)d_in[2];
  const float* b_attn    = (const float*)d_in[3];
  const float* w_proj    = (const float*)d_in[4];
  const float* b_proj    = (const float*)d_in[5];
  const float* ln1_w     = (const float*)d_in[6];
  const float* ln1_b     = (const float*)d_in[7];
  const float* ln2_w     = (const float*)d_in[8];
  const float* ln2_b     = (const float*)d_in[9];
  const float* w_fc      = (const float*)d_in[10];
  const float* b_fc      = (const float*)d_in[11];
  const float* w_fc_proj = (const float*)d_in[12];
  const float* b_fc_proj = (const float*)d_in[13];

  float* out_x = (float*)d_out;
  float* att   = (float*)d_out + (size_t)BB*TT*CC;

  float *qkv, *x2;
  __nv_bfloat16 *h_hi,*h_lo,*h2_hi,*h2_lo,*y_hi,*y_lo,*m_hi,*m_lo;
  __nv_bfloat16 *wat_hi,*wat_lo,*wp_hi,*wp_lo,*wf_hi,*wf_lo,*wfp_hi,*wfp_lo;
  cudaGetSymbolAddress((void**)&qkv,  g_qkv);
  cudaGetSymbolAddress((void**)&x2,   g_x2);
  cudaGetSymbolAddress((void**)&h_hi, g_h_hi);  cudaGetSymbolAddress((void**)&h_lo, g_h_lo);
  cudaGetSymbolAddress((void**)&h2_hi,g_h2_hi); cudaGetSymbolAddress((void**)&h2_lo,g_h2_lo);
  cudaGetSymbolAddress((void**)&y_hi, g_y_hi);  cudaGetSymbolAddress((void**)&y_lo, g_y_lo);
  cudaGetSymbolAddress((void**)&m_hi, g_m_hi);  cudaGetSymbolAddress((void**)&m_lo, g_m_lo);
  cudaGetSymbolAddress((void**)&wat_hi,g_wat_hi); cudaGetSymbolAddress((void**)&wat_lo,g_wat_lo);
  cudaGetSymbolAddress((void**)&wp_hi, g_wp_hi);  cudaGetSymbolAddress((void**)&wp_lo, g_wp_lo);
  cudaGetSymbolAddress((void**)&wf_hi, g_wf_hi);  cudaGetSymbolAddress((void**)&wf_lo, g_wf_lo);
  cudaGetSymbolAddress((void**)&wfp_hi,g_wfp_hi); cudaGetSymbolAddress((void**)&wfp_lo,g_wfp_lo);

  const int SMEM = 2*STG_ELEMS*2; // 81920 bytes
  cudaFuncSetAttribute(gemm_mma<0>, cudaFuncAttributeMaxDynamicSharedMemorySize, SMEM);
  cudaFuncSetAttribute(gemm_mma<1>, cudaFuncAttributeMaxDynamicSharedMemorySize, SMEM);
  cudaFuncSetAttribute(gemm_mma<2>, cudaFuncAttributeMaxDynamicSharedMemorySize, SMEM);

  const int M = BB*TT;  // 4096
  dim3 wb(32,8);

  wsplitT<<<dim3(C3/32,   CC/32),   wb>>>(w_attn,    wat_hi, wat_lo, CC,   C3);
  wsplitT<<<dim3(CC/32,   CC/32),   wb>>>(w_proj,    wp_hi,  wp_lo,  CC,   CC);
  wsplitT<<<dim3(4096/32, CC/32),   wb>>>(w_fc,      wf_hi,  wf_lo,  CC,   4096);
  wsplitT<<<dim3(CC/32,   4096/32), wb>>>(w_fc_proj, wfp_hi, wfp_lo, 4096, CC);

  ln_split<<<M, 256>>>(x, ln1_w, ln1_b, h_hi, h_lo);

  gemm_mma<0><<<dim3(C3/128, M/128), 256, SMEM>>>(h_hi, h_lo, wat_hi, wat_lo,
      b_attn, nullptr, qkv, nullptr, nullptr, M, C3, CC);

  attn_scores<<<dim3(TT/128, TT/128, BB*HH), 256>>>(qkv, att);
  softmax_kernel<<<BB*HH*TT, 256>>>(att);
  attn_av<<<dim3(TT/128, BB*HH), 256>>>(att, qkv, y_hi, y_lo);

  gemm_mma<2><<<dim3(CC/128, M/128), 256, SMEM>>>(y_hi, y_lo, wp_hi, wp_lo,
      b_proj, x, x2, nullptr, nullptr, M, CC, CC);

  ln_split<<<M, 256>>>(x2, ln2_w, ln2_b, h2_hi, h2_lo);

  gemm_mma<1><<<dim3(4096/128, M/128), 256, SMEM>>>(h2_hi, h2_lo, wf_hi, wf_lo,
      b_fc, nullptr, nullptr, m_hi, m_lo, M, 4096, CC);

  gemm_mma<2><<<dim3(CC/128, M/128), 256, SMEM>>>(m_hi, m_lo, wfp_hi, wfp_lo,
      b_fc_proj, x2, out_x, nullptr, nullptr, M, CC, 4096);
}

// round 7
// speedup vs baseline: 2.2990x; 1.1826x over previous
#include <cuda_runtime.h>
#include <cuda_bf16.h>
#include <math.h>
#include <stdint.h>

#define BB 2
#define TT 2048
#define CC 1024
#define C3 3072
#define HH 16
#define HD 64
#define MM 4096

// ---------------- scratch (static device globals; allocation-free) ----------------
__device__ float g_qkv[MM * C3];
__device__ float g_x2 [MM * CC];
__device__ __nv_bfloat16 g_h_hi [MM * CC],   g_h_lo [MM * CC];
__device__ __nv_bfloat16 g_h2_hi[MM * CC],   g_h2_lo[MM * CC];
__device__ __nv_bfloat16 g_y_hi [MM * CC],   g_y_lo [MM * CC];
__device__ __nv_bfloat16 g_m_hi [MM * 4096], g_m_lo [MM * 4096];
__device__ __nv_bfloat16 g_wat_hi[C3 * CC],  g_wat_lo[C3 * CC];
__device__ __nv_bfloat16 g_wp_hi [CC * CC],  g_wp_lo [CC * CC];
__device__ __nv_bfloat16 g_wf_hi [4096 * CC],g_wf_lo [4096 * CC];
__device__ __nv_bfloat16 g_wfp_hi[CC * 4096],g_wfp_lo[CC * 4096];
// per-head attention operands (z = b*16+h)
__device__ __nv_bfloat16 g_q_hi [32*2048*64], g_q_lo [32*2048*64];
__device__ __nv_bfloat16 g_k_hi [32*2048*64], g_k_lo [32*2048*64];
__device__ __nv_bfloat16 g_vT_hi[32*64*2048], g_vT_lo[32*64*2048];

// ---------------- helpers ----------------
__device__ __forceinline__ uint32_t smem_u32(const void* p){
  uint32_t a;
  asm("{ .reg .u64 t; cvta.to.shared.u64 t, %1; cvt.u32.u64 %0, t; }" : "=r"(a) : "l"(p));
  return a;
}
__device__ __forceinline__ void cp16(uint32_t dst, const void* src){
  asm volatile("cp.async.cg.shared.global [%0], [%1], 16;\n" :: "r"(dst), "l"(src));
}
__device__ __forceinline__ void cp_commit(){ asm volatile("cp.async.commit_group;\n"); }
__device__ __forceinline__ void cp_wait1(){ asm volatile("cp.async.wait_group 1;\n" ::: "memory"); }
__device__ __forceinline__ void cp_wait0(){ asm volatile("cp.async.wait_group 0;\n" ::: "memory"); }

__device__ __forceinline__ void mma16816(float* d, const uint32_t* a, uint32_t b0, uint32_t b1){
  asm volatile("mma.sync.aligned.m16n8k16.row.col.f32.bf16.bf16.f32 "
    "{%0,%1,%2,%3}, {%4,%5,%6,%7}, {%8,%9}, {%0,%1,%2,%3};"
    : "+f"(d[0]), "+f"(d[1]), "+f"(d[2]), "+f"(d[3])
    : "r"(a[0]), "r"(a[1]), "r"(a[2]), "r"(a[3]), "r"(b0), "r"(b1));
}

__device__ __forceinline__ float warpReduceSum(float v){
  #pragma unroll
  for (int o=16;o;o>>=1) v += __shfl_xor_sync(0xffffffffu, v, o);
  return v;
}
__device__ __forceinline__ float warpReduceMax(float v){
  #pragma unroll
  for (int o=16;o;o>>=1) v = fmaxf(v, __shfl_xor_sync(0xffffffffu, v, o));
  return v;
}
__device__ float blockReduceSum(float v){
  __shared__ float s[8];
  int lane = threadIdx.x & 31, wid = threadIdx.x >> 5;
  v = warpReduceSum(v);
  __syncthreads();
  if (lane==0) s[wid]=v;
  __syncthreads();
  if (wid==0){
    float t = (lane < 8) ? s[lane] : 0.f;
    t = warpReduceSum(t);
    if (lane==0) s[0]=t;
  }
  __syncthreads();
  return s[0];
}

__device__ __forceinline__ float gelu_f(float x){
  float x3 = x*x*x;
  return 0.5f*x*(1.f + tanhf(0.7978845608028654f*(x + 0.044715f*x3)));
}
__device__ __forceinline__ void split_bf16(float v, __nv_bfloat16& h, __nv_bfloat16& l){
  h = __float2bfloat16(v);
  l = __float2bfloat16(v - __bfloat162float(h));
}

// ---------------- LayerNorm -> bf16 hi/lo pair ----------------
__global__ void __launch_bounds__(256) ln_split(const float* __restrict__ x,
                                                const float* __restrict__ w,
                                                const float* __restrict__ b,
                                                __nv_bfloat16* __restrict__ ohi,
                                                __nv_bfloat16* __restrict__ olo){
  size_t row = blockIdx.x;
  float4 f = ((const float4*)(x + row*CC))[threadIdx.x];
  float mean = blockReduceSum(f.x+f.y+f.z+f.w) * (1.f/CC);
  float dx=f.x-mean, dy=f.y-mean, dz=f.z-mean, dw=f.w-mean;
  float var = blockReduceSum(dx*dx+dy*dy+dz*dz+dw*dw) * (1.f/CC);
  float rs = rsqrtf(var + 1e-5f);
  float4 wv = ((const float4*)w)[threadIdx.x];
  float4 bv = ((const float4*)b)[threadIdx.x];
  float o[4];
  o[0]=dx*rs*wv.x+bv.x; o[1]=dy*rs*wv.y+bv.y; o[2]=dz*rs*wv.z+bv.z; o[3]=dw*rs*wv.w+bv.w;
  __align__(8) __nv_bfloat16 hh[4], ll[4];
  #pragma unroll
  for (int j=0;j<4;j++) split_bf16(o[j], hh[j], ll[j]);
  size_t off = row*CC + threadIdx.x*4;
  *(uint2*)(ohi+off) = *(uint2*)hh;
  *(uint2*)(olo+off) = *(uint2*)ll;
}

// ---------------- weight split+transpose: W[K,N] fp32 -> T[N,K] bf16 hi/lo ----------------
__global__ void wsplitT(const float* __restrict__ W, __nv_bfloat16* __restrict__ Thi,
                        __nv_bfloat16* __restrict__ Tlo, int K, int N){
  __shared__ float t[32][33];
  int n0 = blockIdx.x*32, k0 = blockIdx.y*32;
  int tx = threadIdx.x, ty = threadIdx.y; // (32,8)
  #pragma unroll
  for (int j=0;j<4;j++)
    t[ty+8*j][tx] = W[(size_t)(k0+ty+8*j)*N + n0+tx];
  __syncthreads();
  #pragma unroll
  for (int j=0;j<4;j++){
    int n = ty+8*j;
    float v = t[tx][n];
    __nv_bfloat16 h, l; split_bf16(v, h, l);
    size_t off = (size_t)(n0+n)*K + k0+tx;
    Thi[off]=h; Tlo[off]=l;
  }
}

// ---------------- qkv fp32 -> per-head Q,K bf16 hi/lo [z][t][64] ----------------
__global__ void __launch_bounds__(256) qk_split(const float* __restrict__ qkv,
                                                __nv_bfloat16* __restrict__ qhi, __nv_bfloat16* __restrict__ qlo,
                                                __nv_bfloat16* __restrict__ khi, __nv_bfloat16* __restrict__ klo){
  int r = blockIdx.x;                 // b*2048 + t
  int b = r >> 11, t = r & 2047;
  const float* src = qkv + (size_t)r*C3;
  int c0 = threadIdx.x*8;             // 0..2047
  float4 v0 = *(const float4*)(src + c0);
  float4 v1 = *(const float4*)(src + c0 + 4);
  float vv[8] = {v0.x,v0.y,v0.z,v0.w,v1.x,v1.y,v1.z,v1.w};
  __align__(16) __nv_bfloat16 hh[8], ll[8];
  #pragma unroll
  for (int j=0;j<8;j++) split_bf16(vv[j], hh[j], ll[j]);
  int cc = c0 & 1023;
  int h = cc >> 6, d = cc & 63;
  size_t off = (((size_t)(b*16+h))*2048 + t)*64 + d;
  if (c0 < 1024){
    *(uint4*)(qhi+off) = *(uint4*)hh;
    *(uint4*)(qlo+off) = *(uint4*)ll;
  } else {
    *(uint4*)(khi+off) = *(uint4*)hh;
    *(uint4*)(klo+off) = *(uint4*)ll;
  }
}

// ---------------- qkv v-part -> per-head transposed V bf16 hi/lo [z][d][t] ----------------
__global__ void v_splitT(const float* __restrict__ qkv,
                         __nv_bfloat16* __restrict__ vThi, __nv_bfloat16* __restrict__ vTlo){
  __shared__ float t[32][33];
  int t0 = blockIdx.x*32;        // token tile within batch (64 tiles)
  int d0 = blockIdx.y*32;        // hd tile (2)
  int z  = blockIdx.z;           // b*16+h
  int b = z >> 4, h = z & 15;
  int tx = threadIdx.x, ty = threadIdx.y; // (32,8)
  #pragma unroll
  for (int j=0;j<4;j++){
    int tt = ty+8*j;
    t[tt][tx] = qkv[(size_t)(b*2048 + t0+tt)*C3 + 2048 + h*64 + d0+tx];
  }
  __syncthreads();
  #pragma unroll
  for (int j=0;j<4;j++){
    int d = ty+8*j;
    float v = t[tx][d];
    __nv_bfloat16 hh, ll; split_bf16(v, hh, ll);
    size_t off = ((size_t)z*64 + d0+d)*2048 + t0+tx;
    vThi[off]=hh; vTlo[off]=ll;
  }
}

// ---------------- mma.sync bf16-pair GEMM: C[M,N] = A[M,K] @ B[N,K]^T ----------------
#define STRD 40
#define STG_ELEMS 20480
template<int OP>
__global__ void __launch_bounds__(256) gemm_mma(
    const __nv_bfloat16* __restrict__ Ahi, const __nv_bfloat16* __restrict__ Alo,
    const __nv_bfloat16* __restrict__ Bhi, const __nv_bfloat16* __restrict__ Blo,
    const float* __restrict__ bias, const float* __restrict__ R,
    float* __restrict__ C, __nv_bfloat16* __restrict__ Chi, __nv_bfloat16* __restrict__ Clo,
    int M, int N, int K)
{
  extern __shared__ __nv_bfloat16 sm[];
  const int tid = threadIdx.x, lane = tid & 31, wid = tid >> 5;
  const int wrow = wid >> 1, wcol = wid & 1;
  const int bm = blockIdx.y*128, bn = blockIdx.x*128;
  const uint32_t sb = smem_u32(sm);

  const __nv_bfloat16* Abh = Ahi + (size_t)bm*K;
  const __nv_bfloat16* Abl = Alo + (size_t)bm*K;
  const __nv_bfloat16* Bbh = Bhi + (size_t)bn*K;
  const __nv_bfloat16* Bbl = Blo + (size_t)bn*K;

  const int lrow = tid >> 2;
  const int lseg = tid & 3;

  auto load_stage = [&](int s, int kt){
    uint32_t base = sb + (uint32_t)(s*STG_ELEMS)*2u;
    size_t kof = (size_t)kt*32 + lseg*8;
    #pragma unroll
    for (int r=0; r<2; r++){
      int row = lrow + r*64;
      uint32_t so = base + (uint32_t)(row*STRD + lseg*8)*2u;
      size_t go = (size_t)row*K + kof;
      cp16(so,              Abh + go);
      cp16(so + 5120*2,     Abl + go);
      cp16(so + 10240*2,    Bbh + go);
      cp16(so + 15360*2,    Bbl + go);
    }
    cp_commit();
  };

  float acc[2][8][4];
  #pragma unroll
  for (int mi=0;mi<2;mi++)
    #pragma unroll
    for (int ni=0;ni<8;ni++)
      #pragma unroll
      for (int j=0;j<4;j++) acc[mi][ni][j]=0.f;

  const int NK = K >> 5;
  load_stage(0, 0);

  for (int kt = 0; kt < NK; kt++){
    int s = kt & 1;
    if (kt+1 < NK){ load_stage(s^1, kt+1); cp_wait1(); }
    else          { cp_wait0(); }
    __syncthreads();

    const __nv_bfloat16* As = sm + s*STG_ELEMS;
    const __nv_bfloat16* Bs = As + 10240;
    #pragma unroll
    for (int kk = 0; kk < 2; kk++){
      int k0 = kk*16 + (lane&3)*2;
      uint32_t ah[2][4], al[2][4];
      #pragma unroll
      for (int mi=0;mi<2;mi++){
        int m0 = wrow*32 + mi*16 + (lane>>2);
        ah[mi][0] = *(const uint32_t*)&As[ m0   *STRD + k0  ];
        ah[mi][1] = *(const uint32_t*)&As[(m0+8)*STRD + k0  ];
        ah[mi][2] = *(const uint32_t*)&As[ m0   *STRD + k0+8];
        ah[mi][3] = *(const uint32_t*)&As[(m0+8)*STRD + k0+8];
        al[mi][0] = *(const uint32_t*)&As[5120 +  m0   *STRD + k0  ];
        al[mi][1] = *(const uint32_t*)&As[5120 + (m0+8)*STRD + k0  ];
        al[mi][2] = *(const uint32_t*)&As[5120 +  m0   *STRD + k0+8];
        al[mi][3] = *(const uint32_t*)&As[5120 + (m0+8)*STRD + k0+8];
      }
      #pragma unroll
      for (int ni=0;ni<8;ni++){
        int n0 = wcol*64 + ni*8 + (lane>>2);
        uint32_t bh0 = *(const uint32_t*)&Bs[ n0*STRD + k0  ];
        uint32_t bh1 = *(const uint32_t*)&Bs[ n0*STRD + k0+8];
        uint32_t bl0 = *(const uint32_t*)&Bs[5120 + n0*STRD + k0  ];
        uint32_t bl1 = *(const uint32_t*)&Bs[5120 + n0*STRD + k0+8];
        #pragma unroll
        for (int mi=0;mi<2;mi++){
          mma16816(acc[mi][ni], ah[mi], bh0, bh1);
          mma16816(acc[mi][ni], ah[mi], bl0, bl1);
          mma16816(acc[mi][ni], al[mi], bh0, bh1);
        }
      }
    }
    __syncthreads();
  }

  #pragma unroll
  for (int mi=0;mi<2;mi++){
    int row0 = bm + wrow*32 + mi*16 + (lane>>2);
    #pragma unroll
    for (int ni=0;ni<8;ni++){
      int col = bn + wcol*64 + ni*8 + (lane&3)*2;
      float b0 = bias[col], b1 = bias[col+1];
      float v0 = acc[mi][ni][0] + b0;
      float v1 = acc[mi][ni][1] + b1;
      float v2 = acc[mi][ni][2] + b0;
      float v3 = acc[mi][ni][3] + b1;
      size_t o0 = (size_t)row0*N + col;
      size_t o1 = (size_t)(row0+8)*N + col;
      if (OP == 2){
        float2 r0 = *(const float2*)(R+o0);
        float2 r1 = *(const float2*)(R+o1);
        v0+=r0.x; v1+=r0.y; v2+=r1.x; v3+=r1.y;
      }
      if (OP == 1){
        v0 = gelu_f(v0); v1 = gelu_f(v1); v2 = gelu_f(v2); v3 = gelu_f(v3);
        __nv_bfloat16 h0,l0,h1,l1,h2,l2,h3,l3;
        split_bf16(v0,h0,l0); split_bf16(v1,h1,l1);
        split_bf16(v2,h2,l2); split_bf16(v3,h3,l3);
        *(__nv_bfloat162*)(Chi+o0) = __nv_bfloat162(h0,h1);
        *(__nv_bfloat162*)(Clo+o0) = __nv_bfloat162(l0,l1);
        *(__nv_bfloat162*)(Chi+o1) = __nv_bfloat162(h2,h3);
        *(__nv_bfloat162*)(Clo+o1) = __nv_bfloat162(l2,l3);
      } else {
        *(float2*)(C+o0) = make_float2(v0,v1);
        *(float2*)(C+o1) = make_float2(v2,v3);
      }
    }
  }
}

// ---------------- attention scores (tensor): S = Q K^T / 8, causal tile skip ----------------
// smem (bf16 elems, row stride 72): QH 0, QL 9216, KH 18432, KL 27648 ; total 36864 elems = 73728 B
__global__ void __launch_bounds__(256) attn_scores_mma(
    const __nv_bfloat16* __restrict__ qhi, const __nv_bfloat16* __restrict__ qlo,
    const __nv_bfloat16* __restrict__ khi, const __nv_bfloat16* __restrict__ klo,
    float* __restrict__ att){
  int kt = blockIdx.x, qt = blockIdx.y, z = blockIdx.z;
  if (kt > qt) return;
  extern __shared__ __nv_bfloat16 sm[];
  const int tid = threadIdx.x, lane = tid & 31, wid = tid >> 5;
  const int wrow = wid >> 1, wcol = wid & 1;
  const uint32_t sb = smem_u32(sm);

  const __nv_bfloat16* srcs[4] = {
    qhi + (((size_t)z*2048 + qt*128))*64,
    qlo + (((size_t)z*2048 + qt*128))*64,
    khi + (((size_t)z*2048 + kt*128))*64,
    klo + (((size_t)z*2048 + kt*128))*64 };
  #pragma unroll
  for (int i=0;i<16;i++){
    int f = tid + 256*i;          // 0..4095
    int mat = f >> 10, rem = f & 1023;
    int row = rem >> 3, seg = rem & 7;
    cp16(sb + (uint32_t)(mat*9216 + row*72 + seg*8)*2u, srcs[mat] + (size_t)row*64 + seg*8);
  }
  cp_commit();
  cp_wait0();
  __syncthreads();

  float acc[2][8][4];
  #pragma unroll
  for (int mi=0;mi<2;mi++)
    #pragma unroll
    for (int ni=0;ni<8;ni++)
      #pragma unroll
      for (int j=0;j<4;j++) acc[mi][ni][j]=0.f;

  const __nv_bfloat16* QH = sm;
  const __nv_bfloat16* KH = sm + 18432;
  #pragma unroll
  for (int kk=0; kk<4; kk++){
    int k0 = kk*16 + (lane&3)*2;
    uint32_t ah[2][4], al[2][4];
    #pragma unroll
    for (int mi=0;mi<2;mi++){
      int m0 = wrow*32 + mi*16 + (lane>>2);
      ah[mi][0] = *(const uint32_t*)&QH[ m0   *72 + k0  ];
      ah[mi][1] = *(const uint32_t*)&QH[(m0+8)*72 + k0  ];
      ah[mi][2] = *(const uint32_t*)&QH[ m0   *72 + k0+8];
      ah[mi][3] = *(const uint32_t*)&QH[(m0+8)*72 + k0+8];
      al[mi][0] = *(const uint32_t*)&QH[9216 +  m0   *72 + k0  ];
      al[mi][1] = *(const uint32_t*)&QH[9216 + (m0+8)*72 + k0  ];
      al[mi][2] = *(const uint32_t*)&QH[9216 +  m0   *72 + k0+8];
      al[mi][3] = *(const uint32_t*)&QH[9216 + (m0+8)*72 + k0+8];
    }
    #pragma unroll
    for (int ni=0;ni<8;ni++){
      int n0 = wcol*64 + ni*8 + (lane>>2);
      uint32_t bh0 = *(const uint32_t*)&KH[ n0*72 + k0  ];
      uint32_t bh1 = *(const uint32_t*)&KH[ n0*72 + k0+8];
      uint32_t bl0 = *(const uint32_t*)&KH[9216 + n0*72 + k0  ];
      uint32_t bl1 = *(const uint32_t*)&KH[9216 + n0*72 + k0+8];
      #pragma unroll
      for (int mi=0;mi<2;mi++){
        mma16816(acc[mi][ni], ah[mi], bh0, bh1);
        mma16816(acc[mi][ni], ah[mi], bl0, bl1);
        mma16816(acc[mi][ni], al[mi], bh0, bh1);
      }
    }
  }

  float* out = att + (size_t)z*TT*TT;
  #pragma unroll
  for (int mi=0;mi<2;mi++){
    int row0 = qt*128 + wrow*32 + mi*16 + (lane>>2);
    #pragma unroll
    for (int ni=0;ni<8;ni++){
      int col = kt*128 + wcol*64 + ni*8 + (lane&3)*2;
      size_t o0 = (size_t)row0*TT + col;
      size_t o1 = (size_t)(row0+8)*TT + col;
      *(float2*)(out+o0) = make_float2(acc[mi][ni][0]*0.125f, acc[mi][ni][1]*0.125f);
      *(float2*)(out+o1) = make_float2(acc[mi][ni][2]*0.125f, acc[mi][ni][3]*0.125f);
    }
  }
}

// ---------------- causal softmax: one warp per row, online max/sum + recompute ----------------
__global__ void __launch_bounds__(256) softmax_warp(float* __restrict__ att){
  int lane = threadIdx.x & 31, wid = threadIdx.x >> 5;
  size_t r = (size_t)blockIdx.x*8 + wid;      // 65536 rows
  int q = (int)(r & (TT-1));
  float* row = att + r*(size_t)TT;
  int Lr4 = (((q>>7)+1)*128) >> 2;
  float m = -INFINITY, s = 0.f;
  for (int i=lane; i<Lr4; i+=32){
    float4 v = ((const float4*)row)[i];
    int b4 = i*4;
    float x0 = (b4   <= q) ? v.x : -INFINITY;
    float x1 = (b4+1 <= q) ? v.y : -INFINITY;
    float x2 = (b4+2 <= q) ? v.z : -INFINITY;
    float x3 = (b4+3 <= q) ? v.w : -INFINITY;
    float mv = fmaxf(fmaxf(x0,x1), fmaxf(x2,x3));
    float mnew = fmaxf(m, mv);
    if (mnew > -1e37f){
      s = s*__expf(m - mnew) + __expf(x0-mnew) + __expf(x1-mnew) + __expf(x2-mnew) + __expf(x3-mnew);
      m = mnew;
    }
  }
  float M = warpReduceMax(m);
  s = (m > -1e37f) ? s*__expf(m - M) : 0.f;
  s = warpReduceSum(s);
  float inv = 1.f/s;
  for (int i=lane; i<Lr4; i+=32){
    float4 v = ((const float4*)row)[i];
    int b4 = i*4;
    v.x = (b4   <= q) ? __expf(v.x - M)*inv : 0.f;
    v.y = (b4+1 <= q) ? __expf(v.y - M)*inv : 0.f;
    v.z = (b4+2 <= q) ? __expf(v.z - M)*inv : 0.f;
    v.w = (b4+3 <= q) ? __expf(v.w - M)*inv : 0.f;
    ((float4*)row)[i] = v;
  }
  for (int i=Lr4+lane; i<TT/4; i+=32)
    ((float4*)row)[i] = make_float4(0.f,0.f,0.f,0.f);
}

// ---------------- y = att @ V (tensor): att fp32 -> hi/lo smem, V^T bf16 ----------------
// smem (bf16 elems, row stride 136): AH 0, AL 17408, VH 34816, VL 43520 ; 52224 elems = 104448 B
__global__ void __launch_bounds__(256) attn_av_mma(
    const float* __restrict__ att,
    const __nv_bfloat16* __restrict__ vThi, const __nv_bfloat16* __restrict__ vTlo,
    __nv_bfloat16* __restrict__ yhi, __nv_bfloat16* __restrict__ ylo){
  int qt = 15 - blockIdx.x;      // large qt first
  int z = blockIdx.y;
  int b = z >> 4, h = z & 15;
  extern __shared__ __nv_bfloat16 sm[];
  const int tid = threadIdx.x, lane = tid & 31, wid = tid >> 5;
  const int wrow = wid >> 1, wcol = wid & 1;
  const uint32_t sb = smem_u32(sm);
  __nv_bfloat16* AH = sm;
  __nv_bfloat16* AL = sm + 17408;
  const __nv_bfloat16* VH = sm + 34816;
  const float* arow = att + ((size_t)z*TT + qt*128)*TT;

  float acc[2][4][4];
  #pragma unroll
  for (int mi=0;mi<2;mi++)
    #pragma unroll
    for (int ni=0;ni<4;ni++)
      #pragma unroll
      for (int j=0;j<4;j++) acc[mi][ni][j]=0.f;

  for (int kt = 0; kt <= qt; kt++){
    int t0 = kt*128;
    // V^T hi/lo via cp.async: 2 matrices x 64 rows x 16 segs = 2048 / 256 thr = 8 each
    #pragma unroll
    for (int i=0;i<8;i++){
      int f = tid + 256*i;
      int mat = f >> 10, rem = f & 1023;
      int row = rem >> 4, seg = rem & 15;
      const __nv_bfloat16* src = (mat ? vTlo : vThi) + ((size_t)z*64 + row)*2048 + t0 + seg*8;
      cp16(sb + (uint32_t)((mat ? 43520 : 34816) + row*136 + seg*8)*2u, src);
    }
    cp_commit();
    // att fp32 load + split: 128 rows x 32 float4 = 4096 / 256 = 16 each (warp = one row)
    #pragma unroll
    for (int j=0;j<16;j++){
      int f = tid + 256*j;
      int row = f >> 5, c4 = f & 31;
      float4 v = *(const float4*)(arow + (size_t)row*TT + t0 + c4*4);
      __nv_bfloat16 h0,l0,h1,l1,h2,l2,h3,l3;
      split_bf16(v.x,h0,l0); split_bf16(v.y,h1,l1);
      split_bf16(v.z,h2,l2); split_bf16(v.w,h3,l3);
      int idx = row*136 + c4*4;
      *(__nv_bfloat162*)&AH[idx]   = __nv_bfloat162(h0,h1);
      *(__nv_bfloat162*)&AH[idx+2] = __nv_bfloat162(h2,h3);
      *(__nv_bfloat162*)&AL[idx]   = __nv_bfloat162(l0,l1);
      *(__nv_bfloat162*)&AL[idx+2] = __nv_bfloat162(l2,l3);
    }
    cp_wait0();
    __syncthreads();

    #pragma unroll
    for (int ks=0; ks<8; ks++){
      int k0 = ks*16 + (lane&3)*2;
      uint32_t ah[2][4], al[2][4];
      #pragma unroll
      for (int mi=0;mi<2;mi++){
        int m0 = wrow*32 + mi*16 + (lane>>2);
        ah[mi][0] = *(const uint32_t*)&AH[ m0   *136 + k0  ];
        ah[mi][1] = *(const uint32_t*)&AH[(m0+8)*136 + k0  ];
        ah[mi][2] = *(const uint32_t*)&AH[ m0   *136 + k0+8];
        ah[mi][3] = *(const uint32_t*)&AH[(m0+8)*136 + k0+8];
        al[mi][0] = *(const uint32_t*)&AL[ m0   *136 + k0  ];
        al[mi][1] = *(const uint32_t*)&AL[(m0+8)*136 + k0  ];
        al[mi][2] = *(const uint32_t*)&AL[ m0   *136 + k0+8];
        al[mi][3] = *(const uint32_t*)&AL[(m0+8)*136 + k0+8];
      }
      #pragma unroll
      for (int ni=0;ni<4;ni++){
        int n0 = wcol*32 + ni*8 + (lane>>2);
        uint32_t bh0 = *(const uint32_t*)&VH[ n0*136 + k0  ];
        uint32_t bh1 = *(const uint32_t*)&VH[ n0*136 + k0+8];
        uint32_t bl0 = *(const uint32_t*)&VH[8704 + n0*136 + k0  ];
        uint32_t bl1 = *(const uint32_t*)&VH[8704 + n0*136 + k0+8];
        #pragma unroll
        for (int mi=0;mi<2;mi++){
          mma16816(acc[mi][ni], ah[mi], bh0, bh1);
          mma16816(acc[mi][ni], ah[mi], bl0, bl1);
          mma16816(acc[mi][ni], al[mi], bh0, bh1);
        }
      }
    }
    __syncthreads();
  }

  // epilogue: y[b*T + t][h*64 + hd] bf16 hi/lo
  #pragma unroll
  for (int mi=0;mi<2;mi++){
    int trow = qt*128 + wrow*32 + mi*16 + (lane>>2);
    #pragma unroll
    for (int ni=0;ni<4;ni++){
      int col = h*64 + wcol*32 + ni*8 + (lane&3)*2;
      size_t o0 = ((size_t)(b*TT) + trow)*CC + col;
      size_t o1 = ((size_t)(b*TT) + trow + 8)*CC + col;
      __nv_bfloat16 h0,l0,h1,l1,h2,l2,h3,l3;
      split_bf16(acc[mi][ni][0],h0,l0); split_bf16(acc[mi][ni][1],h1,l1);
      split_bf16(acc[mi][ni][2],h2,l2); split_bf16(acc[mi][ni][3],h3,l3);
      *(__nv_bfloat162*)(yhi+o0) = __nv_bfloat162(h0,h1);
      *(__nv_bfloat162*)(ylo+o0) = __nv_bfloat162(l0,l1);
      *(__nv_bfloat162*)(yhi+o1) = __nv_bfloat162(h2,h3);
      *(__nv_bfloat162*)(ylo+o1) = __nv_bfloat162(l2,l3);
    }
  }
}

// ---------------- launch ----------------
extern "C" void kernel_launch(void* const* d_in, const int* in_sizes, int n_in,
                              void* d_out, int out_size){
  (void)in_sizes; (void)n_in; (void)out_size;
  const float* x         = (const float*)d_in[0];
  const float* w_attn    = (const float*)d_in[2];
  const float* b_attn    = (const float*)d_in[3];
  const float* w_proj    = (const float*)d_in[4];
  const float* b_proj    = (const float*)d_in[5];
  const float* ln1_w     = (const float*)d_in[6];
  const float* ln1_b     = (const float*)d_in[7];
  const float* ln2_w     = (const float*)d_in[8];
  const float* ln2_b     = (const float*)d_in[9];
  const float* w_fc      = (const float*)d_in[10];
  const float* b_fc      = (const float*)d_in[11];
  const float* w_fc_proj = (const float*)d_in[12];
  const float* b_fc_proj = (const float*)d_in[13];

  float* out_x = (float*)d_out;
  float* att   = (float*)d_out + (size_t)BB*TT*CC;

  float *qkv, *x2;
  __nv_bfloat16 *h_hi,*h_lo,*h2_hi,*h2_lo,*y_hi,*y_lo,*m_hi,*m_lo;
  __nv_bfloat16 *wat_hi,*wat_lo,*wp_hi,*wp_lo,*wf_hi,*wf_lo,*wfp_hi,*wfp_lo;
  __nv_bfloat16 *q_hi,*q_lo,*k_hi,*k_lo,*vT_hi,*vT_lo;
  cudaGetSymbolAddress((void**)&qkv,  g_qkv);
  cudaGetSymbolAddress((void**)&x2,   g_x2);
  cudaGetSymbolAddress((void**)&h_hi, g_h_hi);  cudaGetSymbolAddress((void**)&h_lo, g_h_lo);
  cudaGetSymbolAddress((void**)&h2_hi,g_h2_hi); cudaGetSymbolAddress((void**)&h2_lo,g_h2_lo);
  cudaGetSymbolAddress((void**)&y_hi, g_y_hi);  cudaGetSymbolAddress((void**)&y_lo, g_y_lo);
  cudaGetSymbolAddress((void**)&m_hi, g_m_hi);  cudaGetSymbolAddress((void**)&m_lo, g_m_lo);
  cudaGetSymbolAddress((void**)&wat_hi,g_wat_hi); cudaGetSymbolAddress((void**)&wat_lo,g_wat_lo);
  cudaGetSymbolAddress((void**)&wp_hi, g_wp_hi);  cudaGetSymbolAddress((void**)&wp_lo, g_wp_lo);
  cudaGetSymbolAddress((void**)&wf_hi, g_wf_hi);  cudaGetSymbolAddress((void**)&wf_lo, g_wf_lo);
  cudaGetSymbolAddress((void**)&wfp_hi,g_wfp_hi); cudaGetSymbolAddress((void**)&wfp_lo,g_wfp_lo);
  cudaGetSymbolAddress((void**)&q_hi, g_q_hi);   cudaGetSymbolAddress((void**)&q_lo, g_q_lo);
  cudaGetSymbolAddress((void**)&k_hi, g_k_hi);   cudaGetSymbolAddress((void**)&k_lo, g_k_lo);
  cudaGetSymbolAddress((void**)&vT_hi,g_vT_hi);  cudaGetSymbolAddress((void**)&vT_lo,g_vT_lo);

  const int SMEM_G = 2*STG_ELEMS*2;     // 81920
  const int SMEM_S = 36864*2;           // 73728
  const int SMEM_A = 52224*2;           // 104448
  cudaFuncSetAttribute(gemm_mma<0>, cudaFuncAttributeMaxDynamicSharedMemorySize, SMEM_G);
  cudaFuncSetAttribute(gemm_mma<1>, cudaFuncAttributeMaxDynamicSharedMemorySize, SMEM_G);
  cudaFuncSetAttribute(gemm_mma<2>, cudaFuncAttributeMaxDynamicSharedMemorySize, SMEM_G);
  cudaFuncSetAttribute(attn_scores_mma, cudaFuncAttributeMaxDynamicSharedMemorySize, SMEM_S);
  cudaFuncSetAttribute(attn_av_mma, cudaFuncAttributeMaxDynamicSharedMemorySize, SMEM_A);

  const int M = BB*TT;  // 4096
  dim3 wb(32,8);

  wsplitT<<<dim3(C3/32,   CC/32),   wb>>>(w_attn,    wat_hi, wat_lo, CC,   C3);
  wsplitT<<<dim3(CC/32,   CC/32),   wb>>>(w_proj,    wp_hi,  wp_lo,  CC,   CC);
  wsplitT<<<dim3(4096/32, CC/32),   wb>>>(w_fc,      wf_hi,  wf_lo,  CC,   4096);
  wsplitT<<<dim3(CC/32,   4096/32), wb>>>(w_fc_proj, wfp_hi, wfp_lo, 4096, CC);

  ln_split<<<M, 256>>>(x, ln1_w, ln1_b, h_hi, h_lo);

  gemm_mma<0><<<dim3(C3/128, M/128), 256, SMEM_G>>>(h_hi, h_lo, wat_hi, wat_lo,
      b_attn, nullptr, qkv, nullptr, nullptr, M, C3, CC);

  qk_split<<<M, 256>>>(qkv, q_hi, q_lo, k_hi, k_lo);
  v_splitT<<<dim3(64, 2, 32), wb>>>(qkv, vT_hi, vT_lo);

  attn_scores_mma<<<dim3(TT/128, TT/128, BB*HH), 256, SMEM_S>>>(q_hi, q_lo, k_hi, k_lo, att);
  softmax_warp<<<BB*HH*TT/8, 256>>>(att);
  attn_av_mma<<<dim3(TT/128, BB*HH), 256, SMEM_A>>>(att, vT_hi, vT_lo, y_hi, y_lo);

  gemm_mma<2><<<dim3(CC/128, M/128), 256, SMEM_G>>>(y_hi, y_lo, wp_hi, wp_lo,
      b_proj, x, x2, nullptr, nullptr, M, CC, CC);

  ln_split<<<M, 256>>>(x2, ln2_w, ln2_b, h2_hi, h2_lo);

  gemm_mma<1><<<dim3(4096/128, M/128), 256, SMEM_G>>>(h2_hi, h2_lo, wf_hi, wf_lo,
      b_fc, nullptr, nullptr, m_hi, m_lo, M, 4096, CC);

  gemm_mma<2><<<dim3(CC/128, M/128), 256, SMEM_G>>>(m_hi, m_lo, wfp_hi, wfp_lo,
      b_fc_proj, x2, out_x, nullptr, nullptr, M, CC, 4096);
}

// round 8
// speedup vs baseline: 2.8738x; 1.2500x over previous
#include <cuda_runtime.h>
#include <cuda_bf16.h>
#include <math.h>
#include <stdint.h>

#define BB 2
#define TT 2048
#define CC 1024
#define C3 3072
#define HH 16
#define HD 64
#define MM 4096

// ---------------- scratch (static device globals; allocation-free) ----------------
__device__ float g_qkv [MM * C3];          // only v region written/used
__device__ float g_x2  [MM * CC];
__device__ float g_y   [MM * CC];
__device__ float g_h2  [MM * CC];
__device__ float g_m   [MM * 4096];
__device__ float g_vT  [32*64*2048];
__device__ float g_wpT [CC * CC];
__device__ float g_wfT [4096 * CC];
__device__ float g_wfpT[CC * 4096];
__device__ __nv_bfloat16 g_h_hi [MM * CC],  g_h_lo [MM * CC];
__device__ __nv_bfloat16 g_wat_hi[C3 * CC], g_wat_lo[C3 * CC];
__device__ __nv_bfloat16 g_q_hi [32*2048*64], g_q_lo [32*2048*64];
__device__ __nv_bfloat16 g_k_hi [32*2048*64], g_k_lo [32*2048*64];

// ---------------- helpers ----------------
__device__ __forceinline__ uint32_t smem_u32(const void* p){
  uint32_t a;
  asm("{ .reg .u64 t; cvta.to.shared.u64 t, %1; cvt.u32.u64 %0, t; }" : "=r"(a) : "l"(p));
  return a;
}
__device__ __forceinline__ void cp16(uint32_t dst, const void* src){
  asm volatile("cp.async.cg.shared.global [%0], [%1], 16;\n" :: "r"(dst), "l"(src));
}
__device__ __forceinline__ void cp_commit(){ asm volatile("cp.async.commit_group;\n"); }
__device__ __forceinline__ void cp_wait1(){ asm volatile("cp.async.wait_group 1;\n" ::: "memory"); }
__device__ __forceinline__ void cp_wait0(){ asm volatile("cp.async.wait_group 0;\n" ::: "memory"); }

__device__ __forceinline__ void mma16816(float* d, const uint32_t* a, uint32_t b0, uint32_t b1){
  asm volatile("mma.sync.aligned.m16n8k16.row.col.f32.bf16.bf16.f32 "
    "{%0,%1,%2,%3}, {%4,%5,%6,%7}, {%8,%9}, {%0,%1,%2,%3};"
    : "+f"(d[0]), "+f"(d[1]), "+f"(d[2]), "+f"(d[3])
    : "r"(a[0]), "r"(a[1]), "r"(a[2]), "r"(a[3]), "r"(b0), "r"(b1));
}
__device__ __forceinline__ void mma1688t(float* d, const uint32_t* a, uint32_t b0, uint32_t b1){
  asm volatile("mma.sync.aligned.m16n8k8.row.col.f32.tf32.tf32.f32 "
    "{%0,%1,%2,%3}, {%4,%5,%6,%7}, {%8,%9}, {%0,%1,%2,%3};"
    : "+f"(d[0]), "+f"(d[1]), "+f"(d[2]), "+f"(d[3])
    : "r"(a[0]), "r"(a[1]), "r"(a[2]), "r"(a[3]), "r"(b0), "r"(b1));
}
__device__ __forceinline__ float to_tf32(float v){
  uint32_t u; asm("cvt.rna.tf32.f32 %0, %1;" : "=r"(u) : "f"(v));
  return __uint_as_float(u);
}

__device__ __forceinline__ float warpReduceSum(float v){
  #pragma unroll
  for (int o=16;o;o>>=1) v += __shfl_xor_sync(0xffffffffu, v, o);
  return v;
}
__device__ __forceinline__ float warpReduceMax(float v){
  #pragma unroll
  for (int o=16;o;o>>=1) v = fmaxf(v, __shfl_xor_sync(0xffffffffu, v, o));
  return v;
}
__device__ float blockReduceSum(float v){
  __shared__ float s[8];
  int lane = threadIdx.x & 31, wid = threadIdx.x >> 5;
  v = warpReduceSum(v);
  __syncthreads();
  if (lane==0) s[wid]=v;
  __syncthreads();
  if (wid==0){
    float t = (lane < 8) ? s[lane] : 0.f;
    t = warpReduceSum(t);
    if (lane==0) s[0]=t;
  }
  __syncthreads();
  return s[0];
}

__device__ __forceinline__ float gelu_f(float x){
  float x3 = x*x*x;
  return 0.5f*x*(1.f + tanhf(0.7978845608028654f*(x + 0.044715f*x3)));
}
__device__ __forceinline__ void split_bf16(float v, __nv_bfloat16& h, __nv_bfloat16& l){
  h = __float2bfloat16(v);
  l = __float2bfloat16(v - __bfloat162float(h));
}

// ---------------- LayerNorm -> bf16 hi/lo pair (ln1) ----------------
__global__ void __launch_bounds__(256) ln_split(const float* __restrict__ x,
                                                const float* __restrict__ w,
                                                const float* __restrict__ b,
                                                __nv_bfloat16* __restrict__ ohi,
                                                __nv_bfloat16* __restrict__ olo){
  size_t row = blockIdx.x;
  float4 f = ((const float4*)(x + row*CC))[threadIdx.x];
  float mean = blockReduceSum(f.x+f.y+f.z+f.w) * (1.f/CC);
  float dx=f.x-mean, dy=f.y-mean, dz=f.z-mean, dw=f.w-mean;
  float var = blockReduceSum(dx*dx+dy*dy+dz*dz+dw*dw) * (1.f/CC);
  float rs = rsqrtf(var + 1e-5f);
  float4 wv = ((const float4*)w)[threadIdx.x];
  float4 bv = ((const float4*)b)[threadIdx.x];
  float o[4];
  o[0]=dx*rs*wv.x+bv.x; o[1]=dy*rs*wv.y+bv.y; o[2]=dz*rs*wv.z+bv.z; o[3]=dw*rs*wv.w+bv.w;
  __align__(8) __nv_bfloat16 hh[4], ll[4];
  #pragma unroll
  for (int j=0;j<4;j++) split_bf16(o[j], hh[j], ll[j]);
  size_t off = row*CC + threadIdx.x*4;
  *(uint2*)(ohi+off) = *(uint2*)hh;
  *(uint2*)(olo+off) = *(uint2*)ll;
}

// ---------------- LayerNorm -> tf32-rounded fp32 (ln2) ----------------
__global__ void __launch_bounds__(256) ln32(const float* __restrict__ x,
                                            const float* __restrict__ w,
                                            const float* __restrict__ b,
                                            float* __restrict__ out){
  size_t row = blockIdx.x;
  float4 f = ((const float4*)(x + row*CC))[threadIdx.x];
  float mean = blockReduceSum(f.x+f.y+f.z+f.w) * (1.f/CC);
  float dx=f.x-mean, dy=f.y-mean, dz=f.z-mean, dw=f.w-mean;
  float var = blockReduceSum(dx*dx+dy*dy+dz*dz+dw*dw) * (1.f/CC);
  float rs = rsqrtf(var + 1e-5f);
  float4 wv = ((const float4*)w)[threadIdx.x];
  float4 bv = ((const float4*)b)[threadIdx.x];
  float4 o;
  o.x = to_tf32(dx*rs*wv.x+bv.x); o.y = to_tf32(dy*rs*wv.y+bv.y);
  o.z = to_tf32(dz*rs*wv.z+bv.z); o.w = to_tf32(dw*rs*wv.w+bv.w);
  ((float4*)(out + row*CC))[threadIdx.x] = o;
}

// ---------------- weight split+transpose (bf16 pair; w_attn) ----------------
__global__ void wsplitT(const float* __restrict__ W, __nv_bfloat16* __restrict__ Thi,
                        __nv_bfloat16* __restrict__ Tlo, int K, int N){
  __shared__ float t[32][33];
  int n0 = blockIdx.x*32, k0 = blockIdx.y*32;
  int tx = threadIdx.x, ty = threadIdx.y;
  #pragma unroll
  for (int j=0;j<4;j++)
    t[ty+8*j][tx] = W[(size_t)(k0+ty+8*j)*N + n0+tx];
  __syncthreads();
  #pragma unroll
  for (int j=0;j<4;j++){
    int n = ty+8*j;
    float v = t[tx][n];
    __nv_bfloat16 h, l; split_bf16(v, h, l);
    size_t off = (size_t)(n0+n)*K + k0+tx;
    Thi[off]=h; Tlo[off]=l;
  }
}

// ---------------- weight transpose fp32 (tf32-rounded) ----------------
__global__ void wT32(const float* __restrict__ W, float* __restrict__ T, int K, int N){
  __shared__ float t[32][33];
  int n0 = blockIdx.x*32, k0 = blockIdx.y*32;
  int tx = threadIdx.x, ty = threadIdx.y;
  #pragma unroll
  for (int j=0;j<4;j++)
    t[ty+8*j][tx] = W[(size_t)(k0+ty+8*j)*N + n0+tx];
  __syncthreads();
  #pragma unroll
  for (int j=0;j<4;j++){
    int n = ty+8*j;
    T[(size_t)(n0+n)*K + k0+tx] = to_tf32(t[tx][n]);
  }
}

// ---------------- v region -> per-head transposed V fp32 [z][d][t] ----------------
__global__ void v_splitT32(const float* __restrict__ qkv, float* __restrict__ vT){
  __shared__ float t[32][33];
  int t0 = blockIdx.x*32, d0 = blockIdx.y*32, z = blockIdx.z;
  int b = z >> 4, h = z & 15;
  int tx = threadIdx.x, ty = threadIdx.y;
  #pragma unroll
  for (int j=0;j<4;j++){
    int tt = ty+8*j;
    t[tt][tx] = qkv[(size_t)(b*2048 + t0+tt)*C3 + 2048 + h*64 + d0+tx];
  }
  __syncthreads();
  #pragma unroll
  for (int j=0;j<4;j++){
    int d = ty+8*j;
    vT[((size_t)z*64 + d0+d)*2048 + t0+tx] = to_tf32(t[tx][d]);
  }
}

// ---------------- qkv GEMM (bf16-pair) with fused q/k split epilogue ----------------
#define STRD 40
#define STG_ELEMS 20480
__global__ void __launch_bounds__(256) gemm_qkv(
    const __nv_bfloat16* __restrict__ Ahi, const __nv_bfloat16* __restrict__ Alo,
    const __nv_bfloat16* __restrict__ Bhi, const __nv_bfloat16* __restrict__ Blo,
    const float* __restrict__ bias,
    __nv_bfloat16* __restrict__ qhi, __nv_bfloat16* __restrict__ qlo,
    __nv_bfloat16* __restrict__ khi, __nv_bfloat16* __restrict__ klo,
    float* __restrict__ qkv)
{
  const int K = CC, N = C3;
  extern __shared__ __nv_bfloat16 sm[];
  const int tid = threadIdx.x, lane = tid & 31, wid = tid >> 5;
  const int wrow = wid >> 1, wcol = wid & 1;
  const int bm = blockIdx.y*128, bn = blockIdx.x*128;
  const uint32_t sb = smem_u32(sm);

  const __nv_bfloat16* Abh = Ahi + (size_t)bm*K;
  const __nv_bfloat16* Abl = Alo + (size_t)bm*K;
  const __nv_bfloat16* Bbh = Bhi + (size_t)bn*K;
  const __nv_bfloat16* Bbl = Blo + (size_t)bn*K;

  const int lrow = tid >> 2, lseg = tid & 3;
  auto load_stage = [&](int s, int kt){
    uint32_t base = sb + (uint32_t)(s*STG_ELEMS)*2u;
    size_t kof = (size_t)kt*32 + lseg*8;
    #pragma unroll
    for (int r=0; r<2; r++){
      int row = lrow + r*64;
      uint32_t so = base + (uint32_t)(row*STRD + lseg*8)*2u;
      size_t go = (size_t)row*K + kof;
      cp16(so,           Abh + go);
      cp16(so + 10240,   Abl + go);
      cp16(so + 20480,   Bbh + go);
      cp16(so + 30720,   Bbl + go);
    }
    cp_commit();
  };

  float acc[2][8][4];
  #pragma unroll
  for (int mi=0;mi<2;mi++)
    #pragma unroll
    for (int ni=0;ni<8;ni++)
      #pragma unroll
      for (int j=0;j<4;j++) acc[mi][ni][j]=0.f;

  const int NK = K >> 5;
  load_stage(0, 0);
  for (int kt = 0; kt < NK; kt++){
    int s = kt & 1;
    if (kt+1 < NK){ load_stage(s^1, kt+1); cp_wait1(); }
    else          { cp_wait0(); }
    __syncthreads();
    const __nv_bfloat16* As = sm + s*STG_ELEMS;
    const __nv_bfloat16* Bs = As + 10240;
    #pragma unroll
    for (int kk = 0; kk < 2; kk++){
      int k0 = kk*16 + (lane&3)*2;
      uint32_t ah[2][4], al[2][4];
      #pragma unroll
      for (int mi=0;mi<2;mi++){
        int m0 = wrow*32 + mi*16 + (lane>>2);
        ah[mi][0] = *(const uint32_t*)&As[ m0   *STRD + k0  ];
        ah[mi][1] = *(const uint32_t*)&As[(m0+8)*STRD + k0  ];
        ah[mi][2] = *(const uint32_t*)&As[ m0   *STRD + k0+8];
        ah[mi][3] = *(const uint32_t*)&As[(m0+8)*STRD + k0+8];
        al[mi][0] = *(const uint32_t*)&As[5120 +  m0   *STRD + k0  ];
        al[mi][1] = *(const uint32_t*)&As[5120 + (m0+8)*STRD + k0  ];
        al[mi][2] = *(const uint32_t*)&As[5120 +  m0   *STRD + k0+8];
        al[mi][3] = *(const uint32_t*)&As[5120 + (m0+8)*STRD + k0+8];
      }
      #pragma unroll
      for (int ni=0;ni<8;ni++){
        int n0 = wcol*64 + ni*8 + (lane>>2);
        uint32_t bh0 = *(const uint32_t*)&Bs[ n0*STRD + k0  ];
        uint32_t bh1 = *(const uint32_t*)&Bs[ n0*STRD + k0+8];
        uint32_t bl0 = *(const uint32_t*)&Bs[5120 + n0*STRD + k0  ];
        uint32_t bl1 = *(const uint32_t*)&Bs[5120 + n0*STRD + k0+8];
        #pragma unroll
        for (int mi=0;mi<2;mi++){
          mma16816(acc[mi][ni], ah[mi], bh0, bh1);
          mma16816(acc[mi][ni], ah[mi], bl0, bl1);
          mma16816(acc[mi][ni], al[mi], bh0, bh1);
        }
      }
    }
    __syncthreads();
  }

  // epilogue: q/k regions -> bf16 hi/lo split buffers; v region -> fp32 qkv
  #pragma unroll
  for (int mi=0;mi<2;mi++){
    int row0 = bm + wrow*32 + mi*16 + (lane>>2);
    int b_ = row0 >> 11, t_ = row0 & 2047;
    #pragma unroll
    for (int ni=0;ni<8;ni++){
      int col = bn + wcol*64 + ni*8 + (lane&3)*2;
      float b0 = bias[col], b1 = bias[col+1];
      float v0 = acc[mi][ni][0] + b0;
      float v1 = acc[mi][ni][1] + b1;
      float v2 = acc[mi][ni][2] + b0;
      float v3 = acc[mi][ni][3] + b1;
      if (col < 2048){
        int cc = col & 1023, hh = cc >> 6, dd = cc & 63;
        size_t off0 = (((size_t)(b_*16+hh))*2048 + t_)*64 + dd;
        size_t off1 = off0 + 8*64;
        __nv_bfloat16 h0,l0,h1,l1,h2,l2,h3,l3;
        split_bf16(v0,h0,l0); split_bf16(v1,h1,l1);
        split_bf16(v2,h2,l2); split_bf16(v3,h3,l3);
        __nv_bfloat16* dh = (col < 1024) ? qhi : khi;
        __nv_bfloat16* dl = (col < 1024) ? qlo : klo;
        *(__nv_bfloat162*)(dh+off0) = __nv_bfloat162(h0,h1);
        *(__nv_bfloat162*)(dl+off0) = __nv_bfloat162(l0,l1);
        *(__nv_bfloat162*)(dh+off1) = __nv_bfloat162(h2,h3);
        *(__nv_bfloat162*)(dl+off1) = __nv_bfloat162(l2,l3);
      } else {
        size_t o0 = (size_t)row0*C3 + col;
        size_t o1 = (size_t)(row0+8)*C3 + col;
        *(float2*)(qkv+o0) = make_float2(v0,v1);
        *(float2*)(qkv+o1) = make_float2(v2,v3);
      }
    }
  }
}

// ---------------- tf32 GEMM: C[M,N] = A[M,K] @ B[N,K]^T ----------------
// OP 1: C = tf32(gelu(A@B + bias)) ; OP 2: C = A@B + bias + R
#define T32_STRD 36
#define T32_STG 9216
template<int OP>
__global__ void __launch_bounds__(256) gemm_t32(
    const float* __restrict__ A, const float* __restrict__ B,
    const float* __restrict__ bias, const float* __restrict__ R,
    float* __restrict__ C, int M, int N, int K)
{
  extern __shared__ float smf[];
  const int tid = threadIdx.x, lane = tid & 31, wid = tid >> 5;
  const int wrow = wid >> 1, wcol = wid & 1;
  const int bm = blockIdx.y*128, bn = blockIdx.x*128;
  const uint32_t sb = smem_u32(smf);

  const float* Ab = A + (size_t)bm*K;
  const float* Bb = B + (size_t)bn*K;

  auto load_stage = [&](int s, int kt){
    uint32_t base = sb + (uint32_t)(s*T32_STG)*4u;
    #pragma unroll
    for (int i=0;i<8;i++){
      int f = tid + 256*i;                 // 0..2047
      int mat = f >> 10, rem = f & 1023;
      int row = rem >> 3, seg = rem & 7;
      uint32_t so = base + (uint32_t)(mat*4608 + row*T32_STRD + seg*4)*4u;
      const float* src = (mat ? Bb : Ab) + (size_t)row*K + kt*32 + seg*4;
      cp16(so, src);
    }
    cp_commit();
  };

  float acc[2][8][4];
  #pragma unroll
  for (int mi=0;mi<2;mi++)
    #pragma unroll
    for (int ni=0;ni<8;ni++)
      #pragma unroll
      for (int j=0;j<4;j++) acc[mi][ni][j]=0.f;

  const int NK = K >> 5;
  load_stage(0, 0);
  for (int kt = 0; kt < NK; kt++){
    int s = kt & 1;
    if (kt+1 < NK){ load_stage(s^1, kt+1); cp_wait1(); }
    else          { cp_wait0(); }
    __syncthreads();
    const float* As = smf + s*T32_STG;
    const float* Bs = As + 4608;
    #pragma unroll
    for (int ks = 0; ks < 4; ks++){
      int kq = ks*8 + (lane&3);
      uint32_t a[2][4];
      #pragma unroll
      for (int mi=0;mi<2;mi++){
        int m0 = wrow*32 + mi*16 + (lane>>2);
        a[mi][0] = *(const uint32_t*)&As[ m0   *T32_STRD + kq  ];
        a[mi][1] = *(const uint32_t*)&As[(m0+8)*T32_STRD + kq  ];
        a[mi][2] = *(const uint32_t*)&As[ m0   *T32_STRD + kq+4];
        a[mi][3] = *(const uint32_t*)&As[(m0+8)*T32_STRD + kq+4];
      }
      #pragma unroll
      for (int ni=0;ni<8;ni++){
        int n0 = wcol*64 + ni*8 + (lane>>2);
        uint32_t b0 = *(const uint32_t*)&Bs[n0*T32_STRD + kq  ];
        uint32_t b1 = *(const uint32_t*)&Bs[n0*T32_STRD + kq+4];
        mma1688t(acc[0][ni], a[0], b0, b1);
        mma1688t(acc[1][ni], a[1], b0, b1);
      }
    }
    __syncthreads();
  }

  #pragma unroll
  for (int mi=0;mi<2;mi++){
    int row0 = bm + wrow*32 + mi*16 + (lane>>2);
    #pragma unroll
    for (int ni=0;ni<8;ni++){
      int col = bn + wcol*64 + ni*8 + (lane&3)*2;
      float b0 = bias[col], b1 = bias[col+1];
      float v0 = acc[mi][ni][0] + b0;
      float v1 = acc[mi][ni][1] + b1;
      float v2 = acc[mi][ni][2] + b0;
      float v3 = acc[mi][ni][3] + b1;
      size_t o0 = (size_t)row0*N + col;
      size_t o1 = (size_t)(row0+8)*N + col;
      if (OP == 2){
        float2 r0 = *(const float2*)(R+o0);
        float2 r1 = *(const float2*)(R+o1);
        v0+=r0.x; v1+=r0.y; v2+=r1.x; v3+=r1.y;
        *(float2*)(C+o0) = make_float2(v0,v1);
        *(float2*)(C+o1) = make_float2(v2,v3);
      } else {
        *(float2*)(C+o0) = make_float2(to_tf32(gelu_f(v0)), to_tf32(gelu_f(v1)));
        *(float2*)(C+o1) = make_float2(to_tf32(gelu_f(v2)), to_tf32(gelu_f(v3)));
      }
    }
  }
}

// ---------------- attention scores (bf16-pair tensor), causal tile skip ----------------
__global__ void __launch_bounds__(256) attn_scores_mma(
    const __nv_bfloat16* __restrict__ qhi, const __nv_bfloat16* __restrict__ qlo,
    const __nv_bfloat16* __restrict__ khi, const __nv_bfloat16* __restrict__ klo,
    float* __restrict__ att){
  int kt = blockIdx.x, qt = blockIdx.y, z = blockIdx.z;
  if (kt > qt) return;
  extern __shared__ __nv_bfloat16 sm[];
  const int tid = threadIdx.x, lane = tid & 31, wid = tid >> 5;
  const int wrow = wid >> 1, wcol = wid & 1;
  const uint32_t sb = smem_u32(sm);

  const __nv_bfloat16* srcs[4] = {
    qhi + (((size_t)z*2048 + qt*128))*64,
    qlo + (((size_t)z*2048 + qt*128))*64,
    khi + (((size_t)z*2048 + kt*128))*64,
    klo + (((size_t)z*2048 + kt*128))*64 };
  #pragma unroll
  for (int i=0;i<16;i++){
    int f = tid + 256*i;
    int mat = f >> 10, rem = f & 1023;
    int row = rem >> 3, seg = rem & 7;
    cp16(sb + (uint32_t)(mat*9216 + row*72 + seg*8)*2u, srcs[mat] + (size_t)row*64 + seg*8);
  }
  cp_commit();
  cp_wait0();
  __syncthreads();

  float acc[2][8][4];
  #pragma unroll
  for (int mi=0;mi<2;mi++)
    #pragma unroll
    for (int ni=0;ni<8;ni++)
      #pragma unroll
      for (int j=0;j<4;j++) acc[mi][ni][j]=0.f;

  const __nv_bfloat16* QH = sm;
  const __nv_bfloat16* KH = sm + 18432;
  #pragma unroll
  for (int kk=0; kk<4; kk++){
    int k0 = kk*16 + (lane&3)*2;
    uint32_t ah[2][4], al[2][4];
    #pragma unroll
    for (int mi=0;mi<2;mi++){
      int m0 = wrow*32 + mi*16 + (lane>>2);
      ah[mi][0] = *(const uint32_t*)&QH[ m0   *72 + k0  ];
      ah[mi][1] = *(const uint32_t*)&QH[(m0+8)*72 + k0  ];
      ah[mi][2] = *(const uint32_t*)&QH[ m0   *72 + k0+8];
      ah[mi][3] = *(const uint32_t*)&QH[(m0+8)*72 + k0+8];
      al[mi][0] = *(const uint32_t*)&QH[9216 +  m0   *72 + k0  ];
      al[mi][1] = *(const uint32_t*)&QH[9216 + (m0+8)*72 + k0  ];
      al[mi][2] = *(const uint32_t*)&QH[9216 +  m0   *72 + k0+8];
      al[mi][3] = *(const uint32_t*)&QH[9216 + (m0+8)*72 + k0+8];
    }
    #pragma unroll
    for (int ni=0;ni<8;ni++){
      int n0 = wcol*64 + ni*8 + (lane>>2);
      uint32_t bh0 = *(const uint32_t*)&KH[ n0*72 + k0  ];
      uint32_t bh1 = *(const uint32_t*)&KH[ n0*72 + k0+8];
      uint32_t bl0 = *(const uint32_t*)&KH[9216 + n0*72 + k0  ];
      uint32_t bl1 = *(const uint32_t*)&KH[9216 + n0*72 + k0+8];
      #pragma unroll
      for (int mi=0;mi<2;mi++){
        mma16816(acc[mi][ni], ah[mi], bh0, bh1);
        mma16816(acc[mi][ni], ah[mi], bl0, bl1);
        mma16816(acc[mi][ni], al[mi], bh0, bh1);
      }
    }
  }

  float* out = att + (size_t)z*TT*TT;
  #pragma unroll
  for (int mi=0;mi<2;mi++){
    int row0 = qt*128 + wrow*32 + mi*16 + (lane>>2);
    #pragma unroll
    for (int ni=0;ni<8;ni++){
      int col = kt*128 + wcol*64 + ni*8 + (lane&3)*2;
      size_t o0 = (size_t)row0*TT + col;
      size_t o1 = (size_t)(row0+8)*TT + col;
      *(float2*)(out+o0) = make_float2(acc[mi][ni][0]*0.125f, acc[mi][ni][1]*0.125f);
      *(float2*)(out+o1) = make_float2(acc[mi][ni][2]*0.125f, acc[mi][ni][3]*0.125f);
    }
  }
}

// ---------------- causal softmax: one warp per row ----------------
__global__ void __launch_bounds__(256) softmax_warp(float* __restrict__ att){
  int lane = threadIdx.x & 31, wid = threadIdx.x >> 5;
  size_t r = (size_t)blockIdx.x*8 + wid;
  int q = (int)(r & (TT-1));
  float* row = att + r*(size_t)TT;
  int Lr4 = (((q>>7)+1)*128) >> 2;
  float m = -INFINITY, s = 0.f;
  for (int i=lane; i<Lr4; i+=32){
    float4 v = ((const float4*)row)[i];
    int b4 = i*4;
    float x0 = (b4   <= q) ? v.x : -INFINITY;
    float x1 = (b4+1 <= q) ? v.y : -INFINITY;
    float x2 = (b4+2 <= q) ? v.z : -INFINITY;
    float x3 = (b4+3 <= q) ? v.w : -INFINITY;
    float mv = fmaxf(fmaxf(x0,x1), fmaxf(x2,x3));
    float mnew = fmaxf(m, mv);
    if (mnew > -1e37f){
      s = s*__expf(m - mnew) + __expf(x0-mnew) + __expf(x1-mnew) + __expf(x2-mnew) + __expf(x3-mnew);
      m = mnew;
    }
  }
  float M = warpReduceMax(m);
  s = (m > -1e37f) ? s*__expf(m - M) : 0.f;
  s = warpReduceSum(s);
  float inv = 1.f/s;
  for (int i=lane; i<Lr4; i+=32){
    float4 v = ((const float4*)row)[i];
    int b4 = i*4;
    v.x = (b4   <= q) ? __expf(v.x - M)*inv : 0.f;
    v.y = (b4+1 <= q) ? __expf(v.y - M)*inv : 0.f;
    v.z = (b4+2 <= q) ? __expf(v.z - M)*inv : 0.f;
    v.w = (b4+3 <= q) ? __expf(v.w - M)*inv : 0.f;
    ((float4*)row)[i] = v;
  }
  for (int i=Lr4+lane; i<TT/4; i+=32)
    ((float4*)row)[i] = make_float4(0.f,0.f,0.f,0.f);
}

// ---------------- y = att @ V (tf32): att fp32 direct, V^T fp32 ----------------
// smem floats: stage = A 128x68 (8704) + B 64x68 (4352) = 13056 ; x2 = 104448 B
__global__ void __launch_bounds__(256) attn_av_t32(
    const float* __restrict__ att, const float* __restrict__ vT,
    float* __restrict__ y){
  int qt = 15 - blockIdx.x;
  int z = blockIdx.y;
  int b = z >> 4, h = z & 15;
  extern __shared__ float smf[];
  const int tid = threadIdx.x, lane = tid & 31, wid = tid >> 5;
  const int wrow = wid >> 1, wcol = wid & 1;
  const uint32_t sb = smem_u32(smf);
  const float* arow = att + ((size_t)z*TT + qt*128)*TT;
  const float* vb = vT + (size_t)z*64*2048;

  auto load_chunk = [&](int s, int c){
    int t0 = c*64;
    uint32_t base = sb + (uint32_t)(s*13056)*4u;
    #pragma unroll
    for (int i=0;i<8;i++){
      int f = tid + 256*i;              // A: 0..2047
      int row = f >> 4, seg = f & 15;
      cp16(base + (uint32_t)(row*68 + seg*4)*4u, arow + (size_t)row*TT + t0 + seg*4);
    }
    #pragma unroll
    for (int i=0;i<4;i++){
      int f = tid + 256*i;              // B: 0..1023
      int row = f >> 4, seg = f & 15;
      cp16(base + (uint32_t)(8704 + row*68 + seg*4)*4u, vb + (size_t)row*2048 + t0 + seg*4);
    }
    cp_commit();
  };

  float acc[2][4][4];
  #pragma unroll
  for (int mi=0;mi<2;mi++)
    #pragma unroll
    for (int ni=0;ni<4;ni++)
      #pragma unroll
      for (int j=0;j<4;j++) acc[mi][ni][j]=0.f;

  int nch = (qt+1)*2;
  load_chunk(0, 0);
  for (int c = 0; c < nch; c++){
    int s = c & 1;
    if (c+1 < nch){ load_chunk(s^1, c+1); cp_wait1(); }
    else          { cp_wait0(); }
    __syncthreads();
    const float* As = smf + s*13056;
    const float* Bs = As + 8704;
    #pragma unroll
    for (int ks = 0; ks < 8; ks++){
      int kq = ks*8 + (lane&3);
      uint32_t a[2][4];
      #pragma unroll
      for (int mi=0;mi<2;mi++){
        int m0 = wrow*32 + mi*16 + (lane>>2);
        a[mi][0] = __float_as_uint(to_tf32(As[ m0   *68 + kq  ]));
        a[mi][1] = __float_as_uint(to_tf32(As[(m0+8)*68 + kq  ]));
        a[mi][2] = __float_as_uint(to_tf32(As[ m0   *68 + kq+4]));
        a[mi][3] = __float_as_uint(to_tf32(As[(m0+8)*68 + kq+4]));
      }
      #pragma unroll
      for (int ni=0;ni<4;ni++){
        int n0 = wcol*32 + ni*8 + (lane>>2);
        uint32_t b0 = *(const uint32_t*)&Bs[n0*68 + kq  ];
        uint32_t b1 = *(const uint32_t*)&Bs[n0*68 + kq+4];
        mma1688t(acc[0][ni], a[0], b0, b1);
        mma1688t(acc[1][ni], a[1], b0, b1);
      }
    }
    __syncthreads();
  }

  #pragma unroll
  for (int mi=0;mi<2;mi++){
    int trow = qt*128 + wrow*32 + mi*16 + (lane>>2);
    #pragma unroll
    for (int ni=0;ni<4;ni++){
      int col = h*64 + wcol*32 + ni*8 + (lane&3)*2;
      size_t o0 = ((size_t)(b*TT) + trow)*CC + col;
      size_t o1 = ((size_t)(b*TT) + trow + 8)*CC + col;
      *(float2*)(y+o0) = make_float2(to_tf32(acc[mi][ni][0]), to_tf32(acc[mi][ni][1]));
      *(float2*)(y+o1) = make_float2(to_tf32(acc[mi][ni][2]), to_tf32(acc[mi][ni][3]));
    }
  }
}

// ---------------- launch ----------------
extern "C" void kernel_launch(void* const* d_in, const int* in_sizes, int n_in,
                              void* d_out, int out_size){
  (void)in_sizes; (void)n_in; (void)out_size;
  const float* x         = (const float*)d_in[0];
  const float* w_attn    = (const float*)d_in[2];
  const float* b_attn    = (const float*)d_in[3];
  const float* w_proj    = (const float*)d_in[4];
  const float* b_proj    = (const float*)d_in[5];
  const float* ln1_w     = (const float*)d_in[6];
  const float* ln1_b     = (const float*)d_in[7];
  const float* ln2_w     = (const float*)d_in[8];
  const float* ln2_b     = (const float*)d_in[9];
  const float* w_fc      = (const float*)d_in[10];
  const float* b_fc      = (const float*)d_in[11];
  const float* w_fc_proj = (const float*)d_in[12];
  const float* b_fc_proj = (const float*)d_in[13];

  float* out_x = (float*)d_out;
  float* att   = (float*)d_out + (size_t)BB*TT*CC;

  float *qkv,*x2,*y,*h2,*m,*vT,*wpT,*wfT,*wfpT;
  __nv_bfloat16 *h_hi,*h_lo,*wat_hi,*wat_lo,*q_hi,*q_lo,*k_hi,*k_lo;
  cudaGetSymbolAddress((void**)&qkv,  g_qkv);
  cudaGetSymbolAddress((void**)&x2,   g_x2);
  cudaGetSymbolAddress((void**)&y,    g_y);
  cudaGetSymbolAddress((void**)&h2,   g_h2);
  cudaGetSymbolAddress((void**)&m,    g_m);
  cudaGetSymbolAddress((void**)&vT,   g_vT);
  cudaGetSymbolAddress((void**)&wpT,  g_wpT);
  cudaGetSymbolAddress((void**)&wfT,  g_wfT);
  cudaGetSymbolAddress((void**)&wfpT, g_wfpT);
  cudaGetSymbolAddress((void**)&h_hi, g_h_hi);  cudaGetSymbolAddress((void**)&h_lo, g_h_lo);
  cudaGetSymbolAddress((void**)&wat_hi,g_wat_hi); cudaGetSymbolAddress((void**)&wat_lo,g_wat_lo);
  cudaGetSymbolAddress((void**)&q_hi, g_q_hi);  cudaGetSymbolAddress((void**)&q_lo, g_q_lo);
  cudaGetSymbolAddress((void**)&k_hi, g_k_hi);  cudaGetSymbolAddress((void**)&k_lo, g_k_lo);

  const int SMEM_QKV = 2*STG_ELEMS*2;   // 81920
  const int SMEM_T32 = 2*T32_STG*4;     // 73728
  const int SMEM_S   = 36864*2;         // 73728
  const int SMEM_AV  = 2*13056*4;       // 104448
  cudaFuncSetAttribute(gemm_qkv,   cudaFuncAttributeMaxDynamicSharedMemorySize, SMEM_QKV);
  cudaFuncSetAttribute(gemm_t32<1>,cudaFuncAttributeMaxDynamicSharedMemorySize, SMEM_T32);
  cudaFuncSetAttribute(gemm_t32<2>,cudaFuncAttributeMaxDynamicSharedMemorySize, SMEM_T32);
  cudaFuncSetAttribute(attn_scores_mma, cudaFuncAttributeMaxDynamicSharedMemorySize, SMEM_S);
  cudaFuncSetAttribute(attn_av_t32, cudaFuncAttributeMaxDynamicSharedMemorySize, SMEM_AV);

  const int M = BB*TT;  // 4096
  dim3 wb(32,8);

  wsplitT<<<dim3(C3/32, CC/32), wb>>>(w_attn, wat_hi, wat_lo, CC, C3);
  wT32<<<dim3(CC/32,   CC/32),   wb>>>(w_proj,    wpT,  CC,   CC);
  wT32<<<dim3(4096/32, CC/32),   wb>>>(w_fc,      wfT,  CC,   4096);
  wT32<<<dim3(CC/32,   4096/32), wb>>>(w_fc_proj, wfpT, 4096, CC);

  ln_split<<<M, 256>>>(x, ln1_w, ln1_b, h_hi, h_lo);

  gemm_qkv<<<dim3(C3/128, M/128), 256, SMEM_QKV>>>(h_hi, h_lo, wat_hi, wat_lo,
      b_attn, q_hi, q_lo, k_hi, k_lo, qkv);

  v_splitT32<<<dim3(64, 2, 32), wb>>>(qkv, vT);

  attn_scores_mma<<<dim3(TT/128, TT/128, BB*HH), 256, SMEM_S>>>(q_hi, q_lo, k_hi, k_lo, att);
  softmax_warp<<<BB*HH*TT/8, 256>>>(att);
  attn_av_t32<<<dim3(TT/128, BB*HH), 256, SMEM_AV>>>(att, vT, y);

  gemm_t32<2><<<dim3(CC/128, M/128), 256, SMEM_T32>>>(y, wpT,
      b_proj, x, x2, M, CC, CC);

  ln32<<<M, 256>>>(x2, ln2_w, ln2_b, h2);

  gemm_t32<1><<<dim3(4096/128, M/128), 256, SMEM_T32>>>(h2, wfT,
      b_fc, nullptr, m, M, 4096, CC);

  gemm_t32<2><<<dim3(CC/128, M/128), 256, SMEM_T32>>>(m, wfpT,
      b_fc_proj, x2, out_x, M, CC, 4096);
}